// round 6
// baseline (speedup 1.0000x reference)
#include <cuda_runtime.h>
#include <cstdint>

#define B_ 4
#define S_ 2048
#define D_ 1024
#define H_ 16
#define HD_ 64

// ---------------------------------------------------------------------------
// Scratch (device globals: allocation-free per harness rules)
// ---------------------------------------------------------------------------
__device__ float g_q[B_ * H_ * S_ * HD_];
__device__ float g_k[B_ * H_ * S_ * HD_];
__device__ float g_v[B_ * H_ * S_ * HD_];
__device__ float g_attn[B_ * S_ * D_];

// ---------------------------------------------------------------------------
// PTX helpers
// ---------------------------------------------------------------------------
__device__ __forceinline__ uint32_t cvt_tf32(float x) {
    uint32_t r;
    asm("cvt.rna.tf32.f32 %0, %1;" : "=r"(r) : "f"(x));
    return r;
}
__device__ __forceinline__ void mma_tf32(float* c, const uint32_t* a, const uint32_t* b) {
    asm("mma.sync.aligned.m16n8k8.row.col.f32.tf32.tf32.f32 "
        "{%0,%1,%2,%3}, {%4,%5,%6,%7}, {%8,%9}, {%0,%1,%2,%3};"
        : "+f"(c[0]), "+f"(c[1]), "+f"(c[2]), "+f"(c[3])
        : "r"(a[0]), "r"(a[1]), "r"(a[2]), "r"(a[3]),
          "r"(b[0]), "r"(b[1]));
}

// ---------------------------------------------------------------------------
// tf32 GEMM: C[M,N] = A[M,K] @ W[K,N] + bias.
// Block 128x128x32, 8 warps (2m x 4n), warp tile 64x32.
// Smem holds TF32 BIT PATTERNS (converted once at load) -> inner loop is
// pure LDS(u32)+mma, no cvt on the critical path.
// Register-staged LDG->cvt->STS double buffer, A/B halves split around math
// so only 16 staging regs are live at a time (keeps <=128 regs, 2 CTAs/SM).
// MODE 0: plain store to C; A==nullptr -> read g_attn.
// MODE 1: QKV scatter into g_q/g_k/g_v with (B,H,S,HD) layout.
// ---------------------------------------------------------------------------
#define BM 128
#define BN 128
#define BK 32
#define APITCH 36               // conflict-free A fragment reads
#define BPITCH 136              // conflict-free B fragment reads
#define AS_SZ (BM * APITCH)     // 4608 words
#define BS_SZ (BK * BPITCH)     // 4352 words
#define STAGE_SZ (AS_SZ + BS_SZ)
#define GEMM_SMEM_BYTES (2 * STAGE_SZ * 4)   // 71680 B

template <int MODE>
__global__ __launch_bounds__(256, 2) void gemm_tf32(
    const float* __restrict__ A, const float* __restrict__ W,
    const float* __restrict__ bias, float* __restrict__ C,
    int M, int N, int K)
{
    extern __shared__ uint32_t smu[];

    const float* Asrc = A;
    if (MODE == 0 && A == nullptr) Asrc = (const float*)g_attn;

    const int tid = threadIdx.x;
    const int wid = tid >> 5;
    const int lane = tid & 31;
    const int g = lane >> 2;
    const int t4 = lane & 3;
    const int m0w = (wid >> 2) * 64;
    const int n0w = (wid & 3) * 32;
    const int bm = blockIdx.y * BM;
    const int bn = blockIdx.x * BN;

    // loader geometry (4 chunks of 16B each for A and B)
    const int a_row = tid >> 3;             // +32 per chunk step of 256 ids
    const int a_kc  = (tid & 7) * 4;
    const int b_kr  = tid >> 5;             // +8 per chunk step
    const int b_nc  = (tid & 31) * 4;

    float4 stA[4], stB[4];

    auto ldgA = [&](int kb) {
#pragma unroll
        for (int c = 0; c < 4; ++c)
            stA[c] = *(const float4*)(Asrc + (long)(bm + a_row + c * 32) * K + kb + a_kc);
    };
    auto stsA = [&](int buf) {
        uint32_t* As = smu + buf * STAGE_SZ;
#pragma unroll
        for (int c = 0; c < 4; ++c) {
            uint4 u = make_uint4(cvt_tf32(stA[c].x), cvt_tf32(stA[c].y),
                                 cvt_tf32(stA[c].z), cvt_tf32(stA[c].w));
            *(uint4*)&As[(a_row + c * 32) * APITCH + a_kc] = u;
        }
    };
    auto ldgB = [&](int kb) {
#pragma unroll
        for (int c = 0; c < 4; ++c)
            stB[c] = *(const float4*)(W + (long)(kb + b_kr + c * 8) * N + bn + b_nc);
    };
    auto stsB = [&](int buf) {
        uint32_t* Bs = smu + buf * STAGE_SZ + AS_SZ;
#pragma unroll
        for (int c = 0; c < 4; ++c) {
            uint4 u = make_uint4(cvt_tf32(stB[c].x), cvt_tf32(stB[c].y),
                                 cvt_tf32(stB[c].z), cvt_tf32(stB[c].w));
            *(uint4*)&Bs[(b_kr + c * 8) * BPITCH + b_nc] = u;
        }
    };

    float acc[4][4][4];
#pragma unroll
    for (int ma = 0; ma < 4; ++ma)
#pragma unroll
        for (int na = 0; na < 4; ++na)
#pragma unroll
            for (int i = 0; i < 4; ++i) acc[ma][na][i] = 0.f;

    auto math_half = [&](int buf, int ks0) {
        const uint32_t* As = smu + buf * STAGE_SZ;
        const uint32_t* Bs = As + AS_SZ;
#pragma unroll
        for (int ks = ks0; ks < ks0 + 2; ++ks) {
            const int kk = ks * 8;
            uint32_t af[4][4];
            uint32_t bf[4][2];
#pragma unroll
            for (int ma = 0; ma < 4; ++ma) {
                const uint32_t* p = &As[(m0w + ma * 16 + g) * APITCH + kk + t4];
                af[ma][0] = p[0];
                af[ma][1] = p[8 * APITCH];
                af[ma][2] = p[4];
                af[ma][3] = p[8 * APITCH + 4];
            }
#pragma unroll
            for (int na = 0; na < 4; ++na) {
                const uint32_t* p = &Bs[(kk + t4) * BPITCH + n0w + na * 8 + g];
                bf[na][0] = p[0];
                bf[na][1] = p[4 * BPITCH];
            }
#pragma unroll
            for (int ma = 0; ma < 4; ++ma)
#pragma unroll
                for (int na = 0; na < 4; ++na)
                    mma_tf32(acc[ma][na], af[ma], bf[na]);
        }
    };

    const int NIT = K / BK;
    // prologue: tile 0 into buf 0
    ldgA(0); ldgB(0);
    stsA(0); stsB(0);
    __syncthreads();

    for (int it = 0; it < NIT; ++it) {
        const int buf = it & 1;
        const int nxt = buf ^ 1;
        const bool more = (it + 1 < NIT);
        if (more) ldgA((it + 1) * BK);
        math_half(buf, 0);
        if (more) { stsA(nxt); ldgB((it + 1) * BK); }
        math_half(buf, 2);
        if (more) stsB(nxt);
        __syncthreads();
    }

    // --- epilogue ------------------------------------------------------------
#pragma unroll
    for (int na = 0; na < 4; ++na) {
        const int col = bn + n0w + na * 8 + 2 * t4;
        const float2 bx = *(const float2*)&bias[col];

        if (MODE == 0) {
#pragma unroll
            for (int ma = 0; ma < 4; ++ma) {
                const long r0 = bm + m0w + ma * 16 + g;
                *(float2*)&C[r0 * N + col] =
                    make_float2(acc[ma][na][0] + bx.x, acc[ma][na][1] + bx.y);
                *(float2*)&C[(r0 + 8) * N + col] =
                    make_float2(acc[ma][na][2] + bx.x, acc[ma][na][3] + bx.y);
            }
        } else {
            const int h = col / 192;
            const int rem = col - h * 192;
            const int which = rem >> 6;
            const int d = rem & 63;
            float* dst = (which == 0) ? g_q : (which == 1) ? g_k : g_v;
#pragma unroll
            for (int ma = 0; ma < 4; ++ma) {
                const int m = bm + m0w + ma * 16 + g;
                const int b = m >> 11;
                const int s = m & (S_ - 1);
                const long base = (((long)(b * H_ + h)) * S_ + s) * HD_ + d;
                *(float2*)&dst[base] =
                    make_float2(acc[ma][na][0] + bx.x, acc[ma][na][1] + bx.y);
                *(float2*)&dst[base + 8 * HD_] =
                    make_float2(acc[ma][na][2] + bx.x, acc[ma][na][3] + bx.y);
            }
        }
    }
}

// ---------------------------------------------------------------------------
// Tensor-core flash attention, tf32-patterns-in-smem edition.
// Q/K/V converted to tf32 once at load; softmax stores tf32 probs; Phases A/C
// are pure LDS(u32)+mma. Block = (128-query tile, h, b), 256 thr, 8 warps.
// Only ceil(vlen/64) key tiles (exp underflow vs -1e6 mask is exactly 0).
// ---------------------------------------------------------------------------
#define QT 128
#define AP 68
#define QS_OFF   0
#define KS_OFF   (QT * AP)
#define VS_OFF   (KS_OFF + 64 * AP)
#define SS_OFF   (VS_OFF + 64 * AP)
#define AL_OFF   (SS_OFF + QT * AP)
#define LR_OFF   (AL_OFF + QT)
#define ATTN_SMEM_BYTES ((LR_OFF + QT) * 4)

__global__ __launch_bounds__(256, 2) void attn_tc(const int* __restrict__ val_lens)
{
    extern __shared__ uint32_t sm[];
    uint32_t* Qs  = sm + QS_OFF;         // [q][d]  tf32 pattern, pre-scaled 1/8
    uint32_t* Ks  = sm + KS_OFF;         // [kk][d] tf32 pattern
    uint32_t* VsT = sm + VS_OFF;         // [d][kk] tf32 pattern
    uint32_t* Ssu = sm + SS_OFF;         // [q][kk] float scores -> tf32 probs
    float*    Ssf = (float*)Ssu;
    float* alphas = (float*)(sm + AL_OFF);
    float* lrow   = (float*)(sm + LR_OFF);

    const int q0 = blockIdx.x * QT;
    const int h  = blockIdx.y;
    const int b  = blockIdx.z;
    const int vlen = val_lens[b];
    const int tid = threadIdx.x;
    const int wid = tid >> 5;
    const int lane = tid & 31;
    const int g = lane >> 2;
    const int t4 = lane & 3;
    const int m0 = wid * 16;

    const long headoff = ((long)(b * H_ + h)) * S_ * HD_;
    const float* qbase = g_q + headoff;
    const float* kbase = g_k + headoff;
    const float* vbase = g_v + headoff;

    // Load Q tile: scale by 1/8, convert to tf32 pattern once.
    {
        const int r = tid >> 1;
        const int c0 = (tid & 1) * 32;
        const float* src = qbase + (long)(q0 + r) * HD_ + c0;
        uint32_t* dst = &Qs[r * AP + c0];
#pragma unroll
        for (int j = 0; j < 32; j += 4) {
            float4 v = *(const float4*)(src + j);
            uint4 u = make_uint4(cvt_tf32(v.x * 0.125f), cvt_tf32(v.y * 0.125f),
                                 cvt_tf32(v.z * 0.125f), cvt_tf32(v.w * 0.125f));
            *(uint4*)(dst + j) = u;
        }
    }

    float mrow = -3.0e38f;
    float lacc = 0.f;
    float acc_o[8][4];
#pragma unroll
    for (int na = 0; na < 8; ++na)
#pragma unroll
        for (int i = 0; i < 4; ++i) acc_o[na][i] = 0.f;

    const int ntiles = (vlen + 63) >> 6;
    for (int kt = 0; kt < ntiles; ++kt) {
        // --- K tile: LDG -> cvt -> STS (natural [kk][d]) ---
        {
            const int r = tid >> 2;            // 0..63
            const int dc = (tid & 3) * 16;
            const float* src = kbase + (long)(kt * 64 + r) * HD_ + dc;
#pragma unroll
            for (int j = 0; j < 16; j += 4) {
                float4 v = *(const float4*)(src + j);
                uint4 u = make_uint4(cvt_tf32(v.x), cvt_tf32(v.y),
                                     cvt_tf32(v.z), cvt_tf32(v.w));
                *(uint4*)&Ks[r * AP + dc + j] = u;
            }
        }
        // --- V tile: LDG -> cvt -> transposed STS [d][kk] ---
        {
            const int vr = tid >> 2;
            const int vd0 = (tid & 3) * 16;
            const float* src = vbase + (long)(kt * 64 + vr) * HD_ + vd0;
#pragma unroll
            for (int j = 0; j < 16; j += 4) {
                float4 v = *(const float4*)(src + j);
                VsT[(vd0 + j + 0) * AP + vr] = cvt_tf32(v.x);
                VsT[(vd0 + j + 1) * AP + vr] = cvt_tf32(v.y);
                VsT[(vd0 + j + 2) * AP + vr] = cvt_tf32(v.z);
                VsT[(vd0 + j + 3) * AP + vr] = cvt_tf32(v.w);
            }
        }
        __syncthreads();

        // --- Phase A: S = Qs * Ks^T (pure LDS+mma) ---
        {
            float accs[8][4];
#pragma unroll
            for (int na = 0; na < 8; ++na)
#pragma unroll
                for (int i = 0; i < 4; ++i) accs[na][i] = 0.f;
#pragma unroll
            for (int kk = 0; kk < 64; kk += 8) {
                uint32_t af[4];
                const uint32_t* p = &Qs[(m0 + g) * AP + kk + t4];
                af[0] = p[0];
                af[1] = p[8 * AP];
                af[2] = p[4];
                af[3] = p[8 * AP + 4];
#pragma unroll
                for (int na = 0; na < 8; ++na) {
                    const uint32_t* q = &Ks[(na * 8 + g) * AP + kk + t4];
                    uint32_t bf[2] = { q[0], q[4] };
                    mma_tf32(accs[na], af, bf);
                }
            }
#pragma unroll
            for (int na = 0; na < 8; ++na) {
                *(float2*)&Ssf[(m0 + g) * AP + na * 8 + 2 * t4] =
                    make_float2(accs[na][0], accs[na][1]);
                *(float2*)&Ssf[(m0 + g + 8) * AP + na * 8 + 2 * t4] =
                    make_float2(accs[na][2], accs[na][3]);
            }
        }
        __syncthreads();

        // --- Phase B: online softmax (2 threads per row); stores tf32 probs ---
        {
            const int r = tid >> 1;
            const int c0 = (tid & 1) * 32;
            const int nvalid = vlen - kt * 64 - c0;
            float* row = &Ssf[r * AP + c0];
            uint32_t* rowu = &Ssu[r * AP + c0];
            float tmax = -3.0e38f;
#pragma unroll
            for (int j = 0; j < 32; ++j) {
                float s = row[j];
                if (j < nvalid) tmax = fmaxf(tmax, s);
            }
            tmax = fmaxf(tmax, __shfl_xor_sync(0xffffffffu, tmax, 1));
            const float mnew = fmaxf(mrow, tmax);
            const float alpha = __expf(mrow - mnew);
            float lsum = 0.f;
#pragma unroll
            for (int j = 0; j < 32; ++j) {
                const float p = (j < nvalid) ? __expf(row[j] - mnew) : 0.f;
                rowu[j] = cvt_tf32(p);
                lsum += p;
            }
            lsum += __shfl_xor_sync(0xffffffffu, lsum, 1);
            lacc = lacc * alpha + lsum;
            mrow = mnew;
            if ((tid & 1) == 0) { alphas[r] = alpha; lrow[r] = lacc; }
        }
        __syncthreads();

        // --- Phase C: O = O*alpha + P * V (pure LDS+mma) ---
        {
            const float a_lo = alphas[m0 + g];
            const float a_hi = alphas[m0 + g + 8];
#pragma unroll
            for (int na = 0; na < 8; ++na) {
                acc_o[na][0] *= a_lo; acc_o[na][1] *= a_lo;
                acc_o[na][2] *= a_hi; acc_o[na][3] *= a_hi;
            }
#pragma unroll
            for (int kk = 0; kk < 64; kk += 8) {
                uint32_t af[4];
                const uint32_t* p = &Ssu[(m0 + g) * AP + kk + t4];
                af[0] = p[0];
                af[1] = p[8 * AP];
                af[2] = p[4];
                af[3] = p[8 * AP + 4];
#pragma unroll
                for (int na = 0; na < 8; ++na) {
                    const uint32_t* q = &VsT[(na * 8 + g) * AP + kk + t4];
                    uint32_t bf[2] = { q[0], q[4] };
                    mma_tf32(acc_o[na], af, bf);
                }
            }
        }
        __syncthreads();   // protect Ks/VsT/Ss before next tile's loads
    }

    // --- epilogue: normalize, write g_attn (B,S,D) ---
    {
        const float li_lo = 1.0f / lrow[m0 + g];
        const float li_hi = 1.0f / lrow[m0 + g + 8];
        const long r0 = (long)b * S_ + q0 + m0 + g;
#pragma unroll
        for (int na = 0; na < 8; ++na) {
            const int col = h * HD_ + na * 8 + 2 * t4;
            *(float2*)&g_attn[r0 * D_ + col] =
                make_float2(acc_o[na][0] * li_lo, acc_o[na][1] * li_lo);
            *(float2*)&g_attn[(r0 + 8) * D_ + col] =
                make_float2(acc_o[na][2] * li_hi, acc_o[na][3] * li_hi);
        }
    }
}

// ---------------------------------------------------------------------------
// Host launcher (graph-capturable: kernel launches only, no allocs/syncs)
// ---------------------------------------------------------------------------
extern "C" void kernel_launch(void* const* d_in, const int* in_sizes, int n_in,
                              void* d_out, int out_size)
{
    const float* x        = (const float*)d_in[0];
    const float* Wqkv     = (const float*)d_in[1];
    const float* bqkv     = (const float*)d_in[2];
    const float* Wout     = (const float*)d_in[3];
    const float* bout     = (const float*)d_in[4];
    const int*   val_lens = (const int*)d_in[5];
    float* out = (float*)d_out;

    cudaFuncSetAttribute(gemm_tf32<1>,
                         cudaFuncAttributeMaxDynamicSharedMemorySize,
                         GEMM_SMEM_BYTES);
    cudaFuncSetAttribute(gemm_tf32<0>,
                         cudaFuncAttributeMaxDynamicSharedMemorySize,
                         GEMM_SMEM_BYTES);
    cudaFuncSetAttribute(attn_tc,
                         cudaFuncAttributeMaxDynamicSharedMemorySize,
                         ATTN_SMEM_BYTES);

    // 1) QKV projection (tensor cores), scattered into (B,H,S,HD) Q/K/V
    {
        dim3 grid((3 * D_) / BN, (B_ * S_) / BM);   // 24 x 64
        gemm_tf32<1><<<grid, 256, GEMM_SMEM_BYTES>>>(
            x, Wqkv, bqkv, nullptr, B_ * S_, 3 * D_, D_);
    }
    // 2) Tensor-core flash attention -> g_attn
    {
        dim3 grid(S_ / QT, H_, B_);                 // 16 x 16 x 4
        attn_tc<<<grid, 256, ATTN_SMEM_BYTES>>>(val_lens);
    }
    // 3) Output projection (tensor cores) -> d_out
    {
        dim3 grid(D_ / BN, (B_ * S_) / BM);         // 8 x 64
        gemm_tf32<0><<<grid, 256, GEMM_SMEM_BYTES>>>(
            nullptr, Wout, bout, out, B_ * S_, D_, D_);
    }
}

// round 8
// speedup vs baseline: 1.0767x; 1.0767x over previous
#include <cuda_runtime.h>
#include <cstdint>

#define B_ 4
#define S_ 2048
#define D_ 1024
#define H_ 16
#define HD_ 64

// ---------------------------------------------------------------------------
// Scratch (device globals; all tensor-core operands live as tf32 bit patterns)
// ---------------------------------------------------------------------------
__device__ uint32_t g_q[B_ * H_ * S_ * HD_];     // tf32 patterns, Q pre-scaled 1/8
__device__ uint32_t g_k[B_ * H_ * S_ * HD_];
__device__ uint32_t g_v[B_ * H_ * S_ * HD_];
__device__ uint32_t g_attn[B_ * S_ * D_];        // tf32 patterns
__device__ uint32_t g_xc[B_ * S_ * D_];          // tf32(x)
__device__ uint32_t g_wqkvT[3 * D_ * D_];        // W^T tf32 patterns (K-major)
__device__ uint32_t g_woutT[D_ * D_];

// ---------------------------------------------------------------------------
// PTX helpers
// ---------------------------------------------------------------------------
__device__ __forceinline__ uint32_t cvt_tf32(float x) {
    uint32_t r;
    asm("cvt.rna.tf32.f32 %0, %1;" : "=r"(r) : "f"(x));
    return r;
}
__device__ __forceinline__ uint32_t smem_u32(const void* p) {
    return (uint32_t)__cvta_generic_to_shared(p);
}
__device__ __forceinline__ void cp_async16(uint32_t dst, const void* src) {
    asm volatile("cp.async.cg.shared.global [%0], [%1], 16;" :: "r"(dst), "l"(src));
}
__device__ __forceinline__ void cp_commit() {
    asm volatile("cp.async.commit_group;" ::: "memory");
}
__device__ __forceinline__ void cp_wait1() {
    asm volatile("cp.async.wait_group 1;" ::: "memory");
}
__device__ __forceinline__ void cp_wait0() {
    asm volatile("cp.async.wait_group 0;" ::: "memory");
}
__device__ __forceinline__ void mma_tf32(float* c, const uint32_t* a, const uint32_t* b) {
    asm("mma.sync.aligned.m16n8k8.row.col.f32.tf32.tf32.f32 "
        "{%0,%1,%2,%3}, {%4,%5,%6,%7}, {%8,%9}, {%0,%1,%2,%3};"
        : "+f"(c[0]), "+f"(c[1]), "+f"(c[2]), "+f"(c[3])
        : "r"(a[0]), "r"(a[1]), "r"(a[2]), "r"(a[3]),
          "r"(b[0]), "r"(b[1]));
}
// ldmatrix: one x4 = full 16x8 tf32 A-fragment; one x2 = full 8x8 B-fragment.
__device__ __forceinline__ void ldsm_x4(uint32_t* r, uint32_t addr) {
    asm volatile("ldmatrix.sync.aligned.m8n8.x4.shared.b16 {%0,%1,%2,%3}, [%4];"
        : "=r"(r[0]), "=r"(r[1]), "=r"(r[2]), "=r"(r[3]) : "r"(addr));
}
__device__ __forceinline__ void ldsm_x2(uint32_t* r, uint32_t addr) {
    asm volatile("ldmatrix.sync.aligned.m8n8.x2.shared.b16 {%0,%1}, [%2];"
        : "=r"(r[0]), "=r"(r[1]) : "r"(addr));
}

// ---------------------------------------------------------------------------
// Prep kernels: x -> tf32 patterns; W -> transposed tf32 patterns (K-major).
// ---------------------------------------------------------------------------
__global__ void cvt_x_kernel(const float* __restrict__ x)
{
    const long i = ((long)blockIdx.x * 256 + threadIdx.x) * 4;
    float4 v = *(const float4*)(x + i);
    uint4 u = make_uint4(cvt_tf32(v.x), cvt_tf32(v.y), cvt_tf32(v.z), cvt_tf32(v.w));
    *(uint4*)&g_xc[i] = u;
}

__global__ void transpose_tf32(const float* __restrict__ W, int K, int N, int which)
{
    __shared__ uint32_t t[32][33];
    uint32_t* WT = which ? g_woutT : g_wqkvT;
    const int nb = blockIdx.x * 32, kb = blockIdx.y * 32;
    const int tx = threadIdx.x, ty = threadIdx.y;
#pragma unroll
    for (int j = 0; j < 32; j += 8)
        t[ty + j][tx] = cvt_tf32(W[(long)(kb + ty + j) * N + nb + tx]);
    __syncthreads();
#pragma unroll
    for (int j = 0; j < 32; j += 8)
        WT[(long)(nb + ty + j) * K + kb + tx] = t[tx][ty + j];
}

// ---------------------------------------------------------------------------
// tf32 GEMM, ldmatrix edition: C[M,N] = A @ W + bias, all operands already
// tf32 patterns in gmem. Block 128x128x32, 8 warps (2m x 4n), warp 64x32.
// Both A and B smem tiles are K-major pitch-36 (row stride = 4 banks ->
// conflict-free LDSM phases). 2-stage cp.async. Zero cvt in the kernel.
// MODE 0: A = g_attn, float C = acc + bias.
// MODE 1: A = g_xc, scatter tf32(acc+bias) into g_q(/8)/g_k/g_v (B,H,S,HD).
// ---------------------------------------------------------------------------
#define BM 128
#define BN 128
#define BK 32
#define PITCH 36
#define TS_SZ (BM * PITCH)               // words per operand tile
#define STAGE_SZ (2 * TS_SZ)
#define GEMM_SMEM_BYTES (2 * STAGE_SZ * 4)   // 73728 B -> 2 CTAs/SM

template <int MODE>
__global__ __launch_bounds__(256, 2) void gemm_ldsm(
    const float* __restrict__ bias, float* __restrict__ C,
    int M, int N, int K)
{
    extern __shared__ uint32_t smu[];
    const uint32_t sb = smem_u32(smu);

    const uint32_t* Au = (MODE == 0) ? g_attn : g_xc;
    const uint32_t* WT = (MODE == 0) ? g_woutT : g_wqkvT;

    const int tid = threadIdx.x;
    const int wid = tid >> 5;
    const int lane = tid & 31;
    const int g = lane >> 2;
    const int t4 = lane & 3;
    const int m0w = (wid >> 2) * 64;
    const int n0w = (wid & 3) * 32;
    const int bm = blockIdx.y * BM;
    const int bn = blockIdx.x * BN;

    // ldmatrix per-lane byte offsets (relative to tile start)
    const uint32_t a_off =
        ((m0w + (lane & 15)) * PITCH + (lane >> 4) * 4) * 4;
    const uint32_t b_off =
        ((n0w + (lane & 7)) * PITCH + ((lane >> 3) & 1) * 4) * 4;

    // loader geometry: 16B chunks, 4 per thread per operand
    const int l_row = tid >> 3;             // +32 per chunk
    const int l_kc  = (tid & 7) * 4;

    auto load_tile = [&](int it) {
        const int kb = it * BK;
        const int buf = it & 1;
        uint32_t dstA = sb + buf * STAGE_SZ * 4;
        uint32_t dstB = dstA + TS_SZ * 4;
#pragma unroll
        for (int c = 0; c < 4; ++c) {
            const int row = l_row + c * 32;
            cp_async16(dstA + (row * PITCH + l_kc) * 4,
                       Au + (long)(bm + row) * K + kb + l_kc);
            cp_async16(dstB + (row * PITCH + l_kc) * 4,
                       WT + (long)(bn + row) * K + kb + l_kc);
        }
        cp_commit();
    };

    float acc[4][4][4];
#pragma unroll
    for (int ma = 0; ma < 4; ++ma)
#pragma unroll
        for (int na = 0; na < 4; ++na)
#pragma unroll
            for (int i = 0; i < 4; ++i) acc[ma][na][i] = 0.f;

    const int NIT = K / BK;
    load_tile(0);

    for (int it = 0; it < NIT; ++it) {
        const bool more = (it + 1 < NIT);
        if (more) { load_tile(it + 1); cp_wait1(); }
        else      { cp_wait0(); }
        __syncthreads();

        const uint32_t abase = sb + (it & 1) * STAGE_SZ * 4 + a_off;
        const uint32_t bbase = sb + (it & 1) * STAGE_SZ * 4 + TS_SZ * 4 + b_off;
#pragma unroll
        for (int ks = 0; ks < 4; ++ks) {
            const int kk = ks * 8;
            uint32_t af[4][4];
            uint32_t bf[4][2];
#pragma unroll
            for (int ma = 0; ma < 4; ++ma)
                ldsm_x4(af[ma], abase + ma * (16 * PITCH * 4) + kk * 4);
#pragma unroll
            for (int na = 0; na < 4; ++na)
                ldsm_x2(bf[na], bbase + na * (8 * PITCH * 4) + kk * 4);
#pragma unroll
            for (int ma = 0; ma < 4; ++ma)
#pragma unroll
                for (int na = 0; na < 4; ++na)
                    mma_tf32(acc[ma][na], af[ma], bf[na]);
        }
        __syncthreads();
    }

    // --- epilogue ------------------------------------------------------------
#pragma unroll
    for (int na = 0; na < 4; ++na) {
        const int col = bn + n0w + na * 8 + 2 * t4;
        const float2 bx = *(const float2*)&bias[col];

        if (MODE == 0) {
#pragma unroll
            for (int ma = 0; ma < 4; ++ma) {
                const long r0 = bm + m0w + ma * 16 + g;
                *(float2*)&C[r0 * N + col] =
                    make_float2(acc[ma][na][0] + bx.x, acc[ma][na][1] + bx.y);
                *(float2*)&C[(r0 + 8) * N + col] =
                    make_float2(acc[ma][na][2] + bx.x, acc[ma][na][3] + bx.y);
            }
        } else {
            const int h = col / 192;
            const int rem = col - h * 192;
            const int which = rem >> 6;
            const int d = rem & 63;
            uint32_t* dst = (which == 0) ? g_q : (which == 1) ? g_k : g_v;
            const float sc = (which == 0) ? 0.125f : 1.0f;   // fold 1/sqrt(64) into Q
#pragma unroll
            for (int ma = 0; ma < 4; ++ma) {
                const int m = bm + m0w + ma * 16 + g;
                const int b = m >> 11;
                const int s = m & (S_ - 1);
                const long base = (((long)(b * H_ + h)) * S_ + s) * HD_ + d;
                uint2 o0 = make_uint2(cvt_tf32((acc[ma][na][0] + bx.x) * sc),
                                      cvt_tf32((acc[ma][na][1] + bx.y) * sc));
                uint2 o1 = make_uint2(cvt_tf32((acc[ma][na][2] + bx.x) * sc),
                                      cvt_tf32((acc[ma][na][3] + bx.y) * sc));
                *(uint2*)&dst[base] = o0;
                *(uint2*)&dst[base + 8 * HD_] = o1;
            }
        }
    }
}

// ---------------------------------------------------------------------------
// Tensor-core flash attention, ldmatrix edition. Q/K/V arrive as tf32
// patterns (Q pre-scaled); inner loops are LDSM + mma only.
// Block = (128-query tile, h, b), 256 thr, 8 warps; warp owns 16 q-rows.
// Only ceil(vlen/64) key tiles (exp underflow vs -1e6 mask is exactly 0).
// ---------------------------------------------------------------------------
#define QT 128
#define AP 68
#define QS_OFF   0
#define KS_OFF   (QT * AP)
#define VS_OFF   (KS_OFF + 64 * AP)
#define SS_OFF   (VS_OFF + 64 * AP)
#define AL_OFF   (SS_OFF + QT * AP)
#define LR_OFF   (AL_OFF + QT)
#define ATTN_SMEM_BYTES ((LR_OFF + QT) * 4)

__global__ __launch_bounds__(256, 2) void attn_tc(const int* __restrict__ val_lens)
{
    extern __shared__ uint32_t sm[];
    uint32_t* Qs  = sm + QS_OFF;         // [q][d]
    uint32_t* Ks  = sm + KS_OFF;         // [kk][d]
    uint32_t* VsT = sm + VS_OFF;         // [d][kk]
    uint32_t* Ssu = sm + SS_OFF;         // [q][kk] float scores -> tf32 probs
    float*    Ssf = (float*)Ssu;
    float* alphas = (float*)(sm + AL_OFF);
    float* lrow   = (float*)(sm + LR_OFF);

    const int q0 = blockIdx.x * QT;
    const int h  = blockIdx.y;
    const int b  = blockIdx.z;
    const int vlen = val_lens[b];
    const int tid = threadIdx.x;
    const int wid = tid >> 5;
    const int lane = tid & 31;
    const int m0 = wid * 16;

    const long headoff = ((long)(b * H_ + h)) * S_ * HD_;
    const uint32_t* qbase = g_q + headoff;
    const uint32_t* kbase = g_k + headoff;
    const uint32_t* vbase = g_v + headoff;

    const uint32_t sb = smem_u32(sm);
    // ldmatrix per-lane byte offsets
    const uint32_t qa_off = ((m0 + (lane & 15)) * AP + (lane >> 4) * 4) * 4;
    const uint32_t nb_off = (((lane & 7)) * AP + ((lane >> 3) & 1) * 4) * 4;
    const uint32_t QS_B = sb + QS_OFF * 4;
    const uint32_t KS_B = sb + KS_OFF * 4;
    const uint32_t VS_B = sb + VS_OFF * 4;
    const uint32_t SS_B = sb + SS_OFF * 4;

    // Load Q tile (already tf32 patterns, pre-scaled)
    {
        const int r = tid >> 1;
        const int c0 = (tid & 1) * 32;
        const uint32_t* src = qbase + (long)(q0 + r) * HD_ + c0;
        uint32_t* dst = &Qs[r * AP + c0];
#pragma unroll
        for (int j = 0; j < 32; j += 4)
            *(uint4*)(dst + j) = *(const uint4*)(src + j);
    }

    float mrow = -3.0e38f;
    float lacc = 0.f;
    float acc_o[8][4];
#pragma unroll
    for (int na = 0; na < 8; ++na)
#pragma unroll
        for (int i = 0; i < 4; ++i) acc_o[na][i] = 0.f;

    const int ntiles = (vlen + 63) >> 6;
    for (int kt = 0; kt < ntiles; ++kt) {
        // K tile copy (natural [kk][d])
        {
            const int r = tid >> 2;
            const int dc = (tid & 3) * 16;
            const uint32_t* src = kbase + (long)(kt * 64 + r) * HD_ + dc;
            uint32_t* dst = &Ks[r * AP + dc];
#pragma unroll
            for (int j = 0; j < 16; j += 4)
                *(uint4*)(dst + j) = *(const uint4*)(src + j);
        }
        // V tile, transposed scatter [d][kk]
        {
            const int vr = tid >> 2;
            const int vd0 = (tid & 3) * 16;
            const uint32_t* src = vbase + (long)(kt * 64 + vr) * HD_ + vd0;
#pragma unroll
            for (int j = 0; j < 16; j += 4) {
                uint4 v = *(const uint4*)(src + j);
                VsT[(vd0 + j + 0) * AP + vr] = v.x;
                VsT[(vd0 + j + 1) * AP + vr] = v.y;
                VsT[(vd0 + j + 2) * AP + vr] = v.z;
                VsT[(vd0 + j + 3) * AP + vr] = v.w;
            }
        }
        __syncthreads();

        // --- Phase A: S = Qs * Ks^T (LDSM + mma) ---
        {
            float accs[8][4];
#pragma unroll
            for (int na = 0; na < 8; ++na)
#pragma unroll
                for (int i = 0; i < 4; ++i) accs[na][i] = 0.f;
#pragma unroll
            for (int kk = 0; kk < 64; kk += 8) {
                uint32_t af[4];
                ldsm_x4(af, QS_B + qa_off + kk * 4);
#pragma unroll
                for (int na = 0; na < 8; ++na) {
                    uint32_t bf[2];
                    ldsm_x2(bf, KS_B + nb_off + na * (8 * AP * 4) + kk * 4);
                    mma_tf32(accs[na], af, bf);
                }
            }
            const int g = lane >> 2, t4 = lane & 3;
#pragma unroll
            for (int na = 0; na < 8; ++na) {
                *(float2*)&Ssf[(m0 + g) * AP + na * 8 + 2 * t4] =
                    make_float2(accs[na][0], accs[na][1]);
                *(float2*)&Ssf[(m0 + g + 8) * AP + na * 8 + 2 * t4] =
                    make_float2(accs[na][2], accs[na][3]);
            }
        }
        __syncthreads();

        // --- Phase B: online softmax (2 threads per row); stores tf32 probs ---
        {
            const int r = tid >> 1;
            const int c0 = (tid & 1) * 32;
            const int nvalid = vlen - kt * 64 - c0;
            float* row = &Ssf[r * AP + c0];
            uint32_t* rowu = &Ssu[r * AP + c0];
            float tmax = -3.0e38f;
#pragma unroll
            for (int j = 0; j < 32; ++j) {
                float s = row[j];
                if (j < nvalid) tmax = fmaxf(tmax, s);
            }
            tmax = fmaxf(tmax, __shfl_xor_sync(0xffffffffu, tmax, 1));
            const float mnew = fmaxf(mrow, tmax);
            const float alpha = __expf(mrow - mnew);
            float lsum = 0.f;
#pragma unroll
            for (int j = 0; j < 32; ++j) {
                const float p = (j < nvalid) ? __expf(row[j] - mnew) : 0.f;
                rowu[j] = cvt_tf32(p);
                lsum += p;
            }
            lsum += __shfl_xor_sync(0xffffffffu, lsum, 1);
            lacc = lacc * alpha + lsum;
            mrow = mnew;
            if ((tid & 1) == 0) { alphas[r] = alpha; lrow[r] = lacc; }
        }
        __syncthreads();

        // --- Phase C: O = O*alpha + P * V (LDSM + mma) ---
        {
            const int g = lane >> 2;
            const float a_lo = alphas[m0 + g];
            const float a_hi = alphas[m0 + g + 8];
#pragma unroll
            for (int na = 0; na < 8; ++na) {
                acc_o[na][0] *= a_lo; acc_o[na][1] *= a_lo;
                acc_o[na][2] *= a_hi; acc_o[na][3] *= a_hi;
            }
#pragma unroll
            for (int kk = 0; kk < 64; kk += 8) {
                uint32_t af[4];
                ldsm_x4(af, SS_B + qa_off + kk * 4);
#pragma unroll
                for (int na = 0; na < 8; ++na) {
                    uint32_t bf[2];
                    ldsm_x2(bf, VS_B + nb_off + na * (8 * AP * 4) + kk * 4);
                    mma_tf32(acc_o[na], af, bf);
                }
            }
        }
        __syncthreads();   // protect Ks/VsT/Ss before next tile's loads
    }

    // --- epilogue: normalize, write g_attn as tf32 patterns (B,S,D) ---
    {
        const int g = lane >> 2, t4 = lane & 3;
        const float li_lo = 1.0f / lrow[m0 + g];
        const float li_hi = 1.0f / lrow[m0 + g + 8];
        const long r0 = (long)b * S_ + q0 + m0 + g;
#pragma unroll
        for (int na = 0; na < 8; ++na) {
            const int col = h * HD_ + na * 8 + 2 * t4;
            *(uint2*)&g_attn[r0 * D_ + col] =
                make_uint2(cvt_tf32(acc_o[na][0] * li_lo),
                           cvt_tf32(acc_o[na][1] * li_lo));
            *(uint2*)&g_attn[(r0 + 8) * D_ + col] =
                make_uint2(cvt_tf32(acc_o[na][2] * li_hi),
                           cvt_tf32(acc_o[na][3] * li_hi));
        }
    }
}

// ---------------------------------------------------------------------------
// Host launcher (graph-capturable: kernel launches only, no allocs/syncs)
// ---------------------------------------------------------------------------
extern "C" void kernel_launch(void* const* d_in, const int* in_sizes, int n_in,
                              void* d_out, int out_size)
{
    const float* x        = (const float*)d_in[0];
    const float* Wqkv     = (const float*)d_in[1];
    const float* bqkv     = (const float*)d_in[2];
    const float* Wout     = (const float*)d_in[3];
    const float* bout     = (const float*)d_in[4];
    const int*   val_lens = (const int*)d_in[5];
    float* out = (float*)d_out;

    cudaFuncSetAttribute(gemm_ldsm<1>,
                         cudaFuncAttributeMaxDynamicSharedMemorySize, GEMM_SMEM_BYTES);
    cudaFuncSetAttribute(gemm_ldsm<0>,
                         cudaFuncAttributeMaxDynamicSharedMemorySize, GEMM_SMEM_BYTES);
    cudaFuncSetAttribute(attn_tc,
                         cudaFuncAttributeMaxDynamicSharedMemorySize, ATTN_SMEM_BYTES);

    // 0) Prep: tf32-pattern conversions/transposes
    cvt_x_kernel<<<(B_ * S_ * D_) / (256 * 4), 256>>>(x);
    {
        dim3 blk(32, 8);
        transpose_tf32<<<dim3((3 * D_) / 32, D_ / 32), blk>>>(Wqkv, D_, 3 * D_, 0);
        transpose_tf32<<<dim3(D_ / 32, D_ / 32), blk>>>(Wout, D_, D_, 1);
    }
    // 1) QKV projection -> scatter tf32 patterns into (B,H,S,HD) Q/K/V
    {
        dim3 grid((3 * D_) / BN, (B_ * S_) / BM);   // 24 x 64
        gemm_ldsm<1><<<grid, 256, GEMM_SMEM_BYTES>>>(bqkv, nullptr, B_ * S_, 3 * D_, D_);
    }
    // 2) Flash attention -> g_attn (tf32 patterns)
    {
        dim3 grid(S_ / QT, H_, B_);                 // 16 x 16 x 4
        attn_tc<<<grid, 256, ATTN_SMEM_BYTES>>>(val_lens);
    }
    // 3) Output projection -> d_out (fp32 + bias)
    {
        dim3 grid(D_ / BN, (B_ * S_) / BM);         // 8 x 64
        gemm_ldsm<0><<<grid, 256, GEMM_SMEM_BYTES>>>(bout, out, B_ * S_, D_, D_);
    }
}

// round 10
// speedup vs baseline: 1.2767x; 1.1857x over previous
#include <cuda_runtime.h>
#include <cstdint>

#define B_ 4
#define S_ 2048
#define D_ 1024
#define H_ 16
#define HD_ 64

// ---------------------------------------------------------------------------
// Scratch (device globals; tensor-core operands live as tf32 bit patterns)
// ---------------------------------------------------------------------------
__device__ uint32_t g_q[B_ * H_ * S_ * HD_];     // tf32 patterns, Q pre-scaled 1/8
__device__ uint32_t g_k[B_ * H_ * S_ * HD_];
__device__ uint32_t g_v[B_ * H_ * S_ * HD_];
__device__ uint32_t g_attn[B_ * S_ * D_];        // tf32 patterns
__device__ uint32_t g_xc[B_ * S_ * D_];          // tf32(x)
__device__ uint32_t g_wqkvT[3 * D_ * D_];        // W^T tf32 patterns (K-major)
__device__ uint32_t g_woutT[D_ * D_];

// ---------------------------------------------------------------------------
// PTX helpers
// ---------------------------------------------------------------------------
__device__ __forceinline__ uint32_t cvt_tf32(float x) {
    uint32_t r;
    asm("cvt.rna.tf32.f32 %0, %1;" : "=r"(r) : "f"(x));
    return r;
}
__device__ __forceinline__ uint32_t smem_u32(const void* p) {
    return (uint32_t)__cvta_generic_to_shared(p);
}
__device__ __forceinline__ void cp_async16(uint32_t dst, const void* src) {
    asm volatile("cp.async.cg.shared.global [%0], [%1], 16;" :: "r"(dst), "l"(src));
}
__device__ __forceinline__ void cp_commit() {
    asm volatile("cp.async.commit_group;" ::: "memory");
}
__device__ __forceinline__ void cp_wait1() {
    asm volatile("cp.async.wait_group 1;" ::: "memory");
}
__device__ __forceinline__ void cp_wait0() {
    asm volatile("cp.async.wait_group 0;" ::: "memory");
}
__device__ __forceinline__ void mma_tf32(float* c, const uint32_t* a, const uint32_t* b) {
    asm("mma.sync.aligned.m16n8k8.row.col.f32.tf32.tf32.f32 "
        "{%0,%1,%2,%3}, {%4,%5,%6,%7}, {%8,%9}, {%0,%1,%2,%3};"
        : "+f"(c[0]), "+f"(c[1]), "+f"(c[2]), "+f"(c[3])
        : "r"(a[0]), "r"(a[1]), "r"(a[2]), "r"(a[3]),
          "r"(b[0]), "r"(b[1]));
}
__device__ __forceinline__ void ldsm_x4(uint32_t* r, uint32_t addr) {
    asm volatile("ldmatrix.sync.aligned.m8n8.x4.shared.b16 {%0,%1,%2,%3}, [%4];"
        : "=r"(r[0]), "=r"(r[1]), "=r"(r[2]), "=r"(r[3]) : "r"(addr));
}
__device__ __forceinline__ void ldsm_x2(uint32_t* r, uint32_t addr) {
    asm volatile("ldmatrix.sync.aligned.m8n8.x2.shared.b16 {%0,%1}, [%2];"
        : "=r"(r[0]), "=r"(r[1]) : "r"(addr));
}

// ---------------------------------------------------------------------------
// Prep kernels
// ---------------------------------------------------------------------------
__global__ void cvt_x_kernel(const float* __restrict__ x)
{
    const long i = ((long)blockIdx.x * 256 + threadIdx.x) * 4;
    float4 v = *(const float4*)(x + i);
    uint4 u = make_uint4(cvt_tf32(v.x), cvt_tf32(v.y), cvt_tf32(v.z), cvt_tf32(v.w));
    *(uint4*)&g_xc[i] = u;
}

__global__ void transpose_tf32(const float* __restrict__ W, int K, int N, int which)
{
    __shared__ uint32_t t[32][33];
    uint32_t* WT = which ? g_woutT : g_wqkvT;
    const int nb = blockIdx.x * 32, kb = blockIdx.y * 32;
    const int tx = threadIdx.x, ty = threadIdx.y;
#pragma unroll
    for (int j = 0; j < 32; j += 8)
        t[ty + j][tx] = cvt_tf32(W[(long)(kb + ty + j) * N + nb + tx]);
    __syncthreads();
#pragma unroll
    for (int j = 0; j < 32; j += 8)
        WT[(long)(nb + ty + j) * K + kb + tx] = t[tx][ty + j];
}

// ---------------------------------------------------------------------------
// tf32 GEMM, ldmatrix + 3-stage cp.async, ONE barrier per K-iter.
// Block 128x128x32, 8 warps (2m x 4n), warp 64x32, K-major pitch-36 tiles.
// MODE 0: A = g_attn, float C = acc + bias.
// MODE 1: A = g_xc, scatter tf32(acc+bias) into g_q(/8)/g_k/g_v (B,H,S,HD).
// ---------------------------------------------------------------------------
#define BM 128
#define BN 128
#define BK 32
#define PITCH 36
#define TS_SZ (BM * PITCH)
#define STAGE_SZ (2 * TS_SZ)
#define NSTAGE 3
#define GEMM_SMEM_BYTES (NSTAGE * STAGE_SZ * 4)   // 110592 B -> 2 CTAs/SM

template <int MODE>
__global__ __launch_bounds__(256, 2) void gemm_ldsm(
    const float* __restrict__ bias, float* __restrict__ C,
    int M, int N, int K)
{
    extern __shared__ uint32_t smu[];
    const uint32_t sb = smem_u32(smu);

    const uint32_t* Au = (MODE == 0) ? g_attn : g_xc;
    const uint32_t* WT = (MODE == 0) ? g_woutT : g_wqkvT;

    const int tid = threadIdx.x;
    const int wid = tid >> 5;
    const int lane = tid & 31;
    const int g = lane >> 2;
    const int t4 = lane & 3;
    const int m0w = (wid >> 2) * 64;
    const int n0w = (wid & 3) * 32;
    const int bm = blockIdx.y * BM;
    const int bn = blockIdx.x * BN;

    const uint32_t a_off = ((m0w + (lane & 15)) * PITCH + (lane >> 4) * 4) * 4;
    const uint32_t b_off = ((n0w + (lane & 7)) * PITCH + ((lane >> 3) & 1) * 4) * 4;

    const int l_row = tid >> 3;
    const int l_kc  = (tid & 7) * 4;

    auto load_tile = [&](int it) {
        const int kb = it * BK;
        uint32_t dstA = sb + (it % NSTAGE) * STAGE_SZ * 4;
        uint32_t dstB = dstA + TS_SZ * 4;
#pragma unroll
        for (int c = 0; c < 4; ++c) {
            const int row = l_row + c * 32;
            cp_async16(dstA + (row * PITCH + l_kc) * 4,
                       Au + (long)(bm + row) * K + kb + l_kc);
            cp_async16(dstB + (row * PITCH + l_kc) * 4,
                       WT + (long)(bn + row) * K + kb + l_kc);
        }
        cp_commit();
    };

    float acc[4][4][4];
#pragma unroll
    for (int ma = 0; ma < 4; ++ma)
#pragma unroll
        for (int na = 0; na < 4; ++na)
#pragma unroll
            for (int i = 0; i < 4; ++i) acc[ma][na][i] = 0.f;

    const int NIT = K / BK;
    load_tile(0);
    load_tile(1);

    for (int it = 0; it < NIT; ++it) {
        cp_wait1();
        __syncthreads();      // stage it%NSTAGE complete & visible to all
        if (it + 2 < NIT) load_tile(it + 2);   // writes stage (it+2)%3; safe:
                                               // readers of that stage passed
                                               // this barrier two iters ago

        const uint32_t abase = sb + (it % NSTAGE) * STAGE_SZ * 4 + a_off;
        const uint32_t bbase = sb + (it % NSTAGE) * STAGE_SZ * 4 + TS_SZ * 4 + b_off;
#pragma unroll
        for (int ks = 0; ks < 4; ++ks) {
            const int kk = ks * 8;
            uint32_t af[4][4];
            uint32_t bf[4][2];
#pragma unroll
            for (int ma = 0; ma < 4; ++ma)
                ldsm_x4(af[ma], abase + ma * (16 * PITCH * 4) + kk * 4);
#pragma unroll
            for (int na = 0; na < 4; ++na)
                ldsm_x2(bf[na], bbase + na * (8 * PITCH * 4) + kk * 4);
#pragma unroll
            for (int ma = 0; ma < 4; ++ma)
#pragma unroll
                for (int na = 0; na < 4; ++na)
                    mma_tf32(acc[ma][na], af[ma], bf[na]);
        }
        // no trailing barrier: next iter's top barrier orders stage reuse
    }

    // --- epilogue ------------------------------------------------------------
#pragma unroll
    for (int na = 0; na < 4; ++na) {
        const int col = bn + n0w + na * 8 + 2 * t4;
        const float2 bx = *(const float2*)&bias[col];

        if (MODE == 0) {
#pragma unroll
            for (int ma = 0; ma < 4; ++ma) {
                const long r0 = bm + m0w + ma * 16 + g;
                *(float2*)&C[r0 * N + col] =
                    make_float2(acc[ma][na][0] + bx.x, acc[ma][na][1] + bx.y);
                *(float2*)&C[(r0 + 8) * N + col] =
                    make_float2(acc[ma][na][2] + bx.x, acc[ma][na][3] + bx.y);
            }
        } else {
            const int h = col / 192;
            const int rem = col - h * 192;
            const int which = rem >> 6;
            const int d = rem & 63;
            uint32_t* dst = (which == 0) ? g_q : (which == 1) ? g_k : g_v;
            const float sc = (which == 0) ? 0.125f : 1.0f;
#pragma unroll
            for (int ma = 0; ma < 4; ++ma) {
                const int m = bm + m0w + ma * 16 + g;
                const int b = m >> 11;
                const int s = m & (S_ - 1);
                const long base = (((long)(b * H_ + h)) * S_ + s) * HD_ + d;
                uint2 o0 = make_uint2(cvt_tf32((acc[ma][na][0] + bx.x) * sc),
                                      cvt_tf32((acc[ma][na][1] + bx.y) * sc));
                uint2 o1 = make_uint2(cvt_tf32((acc[ma][na][2] + bx.x) * sc),
                                      cvt_tf32((acc[ma][na][3] + bx.y) * sc));
                *(uint2*)&dst[base] = o0;
                *(uint2*)&dst[base + 8 * HD_] = o1;
            }
        }
    }
}

// ---------------------------------------------------------------------------
// Flash attention: ldmatrix + IN-REGISTER online softmax.
// Each warp owns 16 q-rows; its Phase-A accs hold the full 16x64 score tile,
// and row quads (lanes g*4+t4) are the shfl-xor(1,2) reduction domain, so
// max/exp/sum never touch smem. Only tf32 probs are stored (for Phase-C
// ldmatrix); m/l/alpha live in registers. 2 full barriers + 1 syncwarp/tile.
// Only ceil(vlen/64) key tiles (exp underflow vs -1e6 mask is exactly 0).
// ---------------------------------------------------------------------------
#define QT 128
#define AP 68
#define QS_OFF   0
#define KS_OFF   (QT * AP)
#define VS_OFF   (KS_OFF + 64 * AP)
#define SS_OFF   (VS_OFF + 64 * AP)
#define ATTN_SMEM_BYTES ((SS_OFF + QT * AP) * 4)   // 104448 B

__global__ __launch_bounds__(256, 2) void attn_tc(const int* __restrict__ val_lens)
{
    extern __shared__ uint32_t sm[];
    uint32_t* Ks  = sm + KS_OFF;         // [kk][d]
    uint32_t* VsT = sm + VS_OFF;         // [d][kk]
    uint32_t* Ssu = sm + SS_OFF;         // [q][kk] tf32 probs (warp-private rows)
    uint32_t* Qs  = sm + QS_OFF;         // [q][d]

    const int q0 = blockIdx.x * QT;
    const int h  = blockIdx.y;
    const int b  = blockIdx.z;
    const int vlen = val_lens[b];
    const int tid = threadIdx.x;
    const int wid = tid >> 5;
    const int lane = tid & 31;
    const int g = lane >> 2;
    const int t4 = lane & 3;
    const int m0 = wid * 16;

    const long headoff = ((long)(b * H_ + h)) * S_ * HD_;
    const uint32_t* qbase = g_q + headoff;
    const uint32_t* kbase = g_k + headoff;
    const uint32_t* vbase = g_v + headoff;

    const uint32_t sb = smem_u32(sm);
    const uint32_t qa_off = ((m0 + (lane & 15)) * AP + (lane >> 4) * 4) * 4;
    const uint32_t nb_off = (((lane & 7)) * AP + ((lane >> 3) & 1) * 4) * 4;
    const uint32_t QS_B = sb + QS_OFF * 4;
    const uint32_t KS_B = sb + KS_OFF * 4;
    const uint32_t VS_B = sb + VS_OFF * 4;
    const uint32_t SS_B = sb + SS_OFF * 4;

    // Load Q tile (tf32 patterns, pre-scaled)
    {
        const int r = tid >> 1;
        const int c0 = (tid & 1) * 32;
        const uint32_t* src = qbase + (long)(q0 + r) * HD_ + c0;
        uint32_t* dst = &Qs[r * AP + c0];
#pragma unroll
        for (int j = 0; j < 32; j += 4)
            *(uint4*)(dst + j) = *(const uint4*)(src + j);
    }

    // Per-lane softmax state for its two rows (replicated within quad)
    float m_lo = -3.0e38f, m_hi = -3.0e38f;
    float l_lo = 0.f, l_hi = 0.f;
    float acc_o[8][4];
#pragma unroll
    for (int na = 0; na < 8; ++na)
#pragma unroll
        for (int i = 0; i < 4; ++i) acc_o[na][i] = 0.f;

    const int ntiles = (vlen + 63) >> 6;
    for (int kt = 0; kt < ntiles; ++kt) {
        // --- K tile via cp.async; V transposed via registers (overlapped) ---
#pragma unroll
        for (int c = 0; c < 4; ++c) {
            const int id = tid + c * 256;
            const int r = id >> 4;
            const int dc = (id & 15) * 4;
            cp_async16(KS_B + (r * AP + dc) * 4,
                       kbase + (long)(kt * 64 + r) * HD_ + dc);
        }
        cp_commit();
        {
            const int vr = tid >> 2;
            const int vd0 = (tid & 3) * 16;
            const uint32_t* src = vbase + (long)(kt * 64 + vr) * HD_ + vd0;
#pragma unroll
            for (int j = 0; j < 16; j += 4) {
                uint4 v = *(const uint4*)(src + j);
                VsT[(vd0 + j + 0) * AP + vr] = v.x;
                VsT[(vd0 + j + 1) * AP + vr] = v.y;
                VsT[(vd0 + j + 2) * AP + vr] = v.z;
                VsT[(vd0 + j + 3) * AP + vr] = v.w;
            }
        }
        cp_wait0();
        __syncthreads();

        // --- Phase A: S = Q K^T (LDSM + mma), then in-register softmax ---
        float accs[8][4];
#pragma unroll
        for (int na = 0; na < 8; ++na)
#pragma unroll
            for (int i = 0; i < 4; ++i) accs[na][i] = 0.f;
#pragma unroll
        for (int kk = 0; kk < 64; kk += 8) {
            uint32_t af[4];
            ldsm_x4(af, QS_B + qa_off + kk * 4);
#pragma unroll
            for (int na = 0; na < 8; ++na) {
                uint32_t bf[2];
                ldsm_x2(bf, KS_B + nb_off + na * (8 * AP * 4) + kk * 4);
                mma_tf32(accs[na], af, bf);
            }
        }

        {   // masked row max (quad shfl reduction)
            const int cbase = kt * 64 + 2 * t4;
            float mx_lo = -3.0e38f, mx_hi = -3.0e38f;
#pragma unroll
            for (int na = 0; na < 8; ++na) {
                const int c0 = cbase + na * 8;
                if (c0 < vlen)     { mx_lo = fmaxf(mx_lo, accs[na][0]);
                                     mx_hi = fmaxf(mx_hi, accs[na][2]); }
                if (c0 + 1 < vlen) { mx_lo = fmaxf(mx_lo, accs[na][1]);
                                     mx_hi = fmaxf(mx_hi, accs[na][3]); }
            }
            mx_lo = fmaxf(mx_lo, __shfl_xor_sync(0xffffffffu, mx_lo, 1));
            mx_lo = fmaxf(mx_lo, __shfl_xor_sync(0xffffffffu, mx_lo, 2));
            mx_hi = fmaxf(mx_hi, __shfl_xor_sync(0xffffffffu, mx_hi, 1));
            mx_hi = fmaxf(mx_hi, __shfl_xor_sync(0xffffffffu, mx_hi, 2));

            const float mn_lo = fmaxf(m_lo, mx_lo);
            const float mn_hi = fmaxf(m_hi, mx_hi);
            const float al_lo = __expf(m_lo - mn_lo);
            const float al_hi = __expf(m_hi - mn_hi);

            float s_lo = 0.f, s_hi = 0.f;
#pragma unroll
            for (int na = 0; na < 8; ++na) {
                const int c0 = cbase + na * 8;
                const float p0 = (c0 < vlen)     ? __expf(accs[na][0] - mn_lo) : 0.f;
                const float p1 = (c0 + 1 < vlen) ? __expf(accs[na][1] - mn_lo) : 0.f;
                const float p2 = (c0 < vlen)     ? __expf(accs[na][2] - mn_hi) : 0.f;
                const float p3 = (c0 + 1 < vlen) ? __expf(accs[na][3] - mn_hi) : 0.f;
                s_lo += p0 + p1;
                s_hi += p2 + p3;
                *(uint2*)&Ssu[(m0 + g) * AP + na * 8 + 2 * t4] =
                    make_uint2(cvt_tf32(p0), cvt_tf32(p1));
                *(uint2*)&Ssu[(m0 + g + 8) * AP + na * 8 + 2 * t4] =
                    make_uint2(cvt_tf32(p2), cvt_tf32(p3));
            }
            s_lo += __shfl_xor_sync(0xffffffffu, s_lo, 1);
            s_lo += __shfl_xor_sync(0xffffffffu, s_lo, 2);
            s_hi += __shfl_xor_sync(0xffffffffu, s_hi, 1);
            s_hi += __shfl_xor_sync(0xffffffffu, s_hi, 2);

            l_lo = l_lo * al_lo + s_lo;
            l_hi = l_hi * al_hi + s_hi;
            m_lo = mn_lo;
            m_hi = mn_hi;

            // rescale O accumulators
#pragma unroll
            for (int na = 0; na < 8; ++na) {
                acc_o[na][0] *= al_lo; acc_o[na][1] *= al_lo;
                acc_o[na][2] *= al_hi; acc_o[na][3] *= al_hi;
            }
        }
        __syncwarp();   // Ssu rows are warp-private; make lane STS visible to LDSM

        // --- Phase C: O += P * V (LDSM + mma) ---
#pragma unroll
        for (int kk = 0; kk < 64; kk += 8) {
            uint32_t af[4];
            ldsm_x4(af, SS_B + qa_off + kk * 4);
#pragma unroll
            for (int na = 0; na < 8; ++na) {
                uint32_t bf[2];
                ldsm_x2(bf, VS_B + nb_off + na * (8 * AP * 4) + kk * 4);
                mma_tf32(acc_o[na], af, bf);
            }
        }
        __syncthreads();   // protect Ks/VsT before next tile's loads
    }

    // --- epilogue: normalize, write g_attn as tf32 patterns (B,S,D) ---
    {
        const float li_lo = 1.0f / l_lo;
        const float li_hi = 1.0f / l_hi;
        const long r0 = (long)b * S_ + q0 + m0 + g;
#pragma unroll
        for (int na = 0; na < 8; ++na) {
            const int col = h * HD_ + na * 8 + 2 * t4;
            *(uint2*)&g_attn[r0 * D_ + col] =
                make_uint2(cvt_tf32(acc_o[na][0] * li_lo),
                           cvt_tf32(acc_o[na][1] * li_lo));
            *(uint2*)&g_attn[(r0 + 8) * D_ + col] =
                make_uint2(cvt_tf32(acc_o[na][2] * li_hi),
                           cvt_tf32(acc_o[na][3] * li_hi));
        }
    }
}

// ---------------------------------------------------------------------------
// Host launcher (graph-capturable: kernel launches only, no allocs/syncs)
// ---------------------------------------------------------------------------
extern "C" void kernel_launch(void* const* d_in, const int* in_sizes, int n_in,
                              void* d_out, int out_size)
{
    const float* x        = (const float*)d_in[0];
    const float* Wqkv     = (const float*)d_in[1];
    const float* bqkv     = (const float*)d_in[2];
    const float* Wout     = (const float*)d_in[3];
    const float* bout     = (const float*)d_in[4];
    const int*   val_lens = (const int*)d_in[5];
    float* out = (float*)d_out;

    cudaFuncSetAttribute(gemm_ldsm<1>,
                         cudaFuncAttributeMaxDynamicSharedMemorySize, GEMM_SMEM_BYTES);
    cudaFuncSetAttribute(gemm_ldsm<0>,
                         cudaFuncAttributeMaxDynamicSharedMemorySize, GEMM_SMEM_BYTES);
    cudaFuncSetAttribute(attn_tc,
                         cudaFuncAttributeMaxDynamicSharedMemorySize, ATTN_SMEM_BYTES);

    // 0) Prep: tf32-pattern conversions/transposes
    cvt_x_kernel<<<(B_ * S_ * D_) / (256 * 4), 256>>>(x);
    {
        dim3 blk(32, 8);
        transpose_tf32<<<dim3((3 * D_) / 32, D_ / 32), blk>>>(Wqkv, D_, 3 * D_, 0);
        transpose_tf32<<<dim3(D_ / 32, D_ / 32), blk>>>(Wout, D_, D_, 1);
    }
    // 1) QKV projection -> tf32-pattern Q/K/V in (B,H,S,HD)
    {
        dim3 grid((3 * D_) / BN, (B_ * S_) / BM);   // 24 x 64
        gemm_ldsm<1><<<grid, 256, GEMM_SMEM_BYTES>>>(bqkv, nullptr, B_ * S_, 3 * D_, D_);
    }
    // 2) Flash attention -> g_attn (tf32 patterns)
    {
        dim3 grid(S_ / QT, H_, B_);                 // 16 x 16 x 4
        attn_tc<<<grid, 256, ATTN_SMEM_BYTES>>>(val_lens);
    }
    // 3) Output projection -> d_out (fp32 + bias)
    {
        dim3 grid(D_ / BN, (B_ * S_) / BM);         // 8 x 64
        gemm_ldsm<0><<<grid, 256, GEMM_SMEM_BYTES>>>(bout, out, B_ * S_, D_, D_);
    }
}

// round 11
// speedup vs baseline: 1.3009x; 1.0190x over previous
#include <cuda_runtime.h>
#include <cstdint>

#define B_ 4
#define S_ 2048
#define D_ 1024
#define H_ 16
#define HD_ 64

// ---------------------------------------------------------------------------
// Scratch (device globals; tensor-core operands live as tf32 bit patterns)
// ---------------------------------------------------------------------------
__device__ uint32_t g_q[B_ * H_ * S_ * HD_];     // tf32 patterns, Q pre-scaled 1/8
__device__ uint32_t g_k[B_ * H_ * S_ * HD_];
__device__ uint32_t g_v[B_ * H_ * S_ * HD_];
__device__ uint32_t g_attn[B_ * S_ * D_];        // tf32 patterns
__device__ uint32_t g_xc[B_ * S_ * D_];          // tf32(x)
__device__ uint32_t g_wqkvT[3 * D_ * D_];        // W^T tf32 patterns (K-major)
__device__ uint32_t g_woutT[D_ * D_];

// ---------------------------------------------------------------------------
// PTX helpers
// ---------------------------------------------------------------------------
__device__ __forceinline__ uint32_t cvt_tf32(float x) {
    uint32_t r;
    asm("cvt.rna.tf32.f32 %0, %1;" : "=r"(r) : "f"(x));
    return r;
}
__device__ __forceinline__ uint32_t smem_u32(const void* p) {
    return (uint32_t)__cvta_generic_to_shared(p);
}
__device__ __forceinline__ void cp_async16(uint32_t dst, const void* src) {
    asm volatile("cp.async.cg.shared.global [%0], [%1], 16;" :: "r"(dst), "l"(src));
}
__device__ __forceinline__ void cp_commit() {
    asm volatile("cp.async.commit_group;" ::: "memory");
}
__device__ __forceinline__ void cp_wait1() {
    asm volatile("cp.async.wait_group 1;" ::: "memory");
}
__device__ __forceinline__ void cp_wait0() {
    asm volatile("cp.async.wait_group 0;" ::: "memory");
}
__device__ __forceinline__ void mma_tf32(float* c, const uint32_t* a, const uint32_t* b) {
    asm("mma.sync.aligned.m16n8k8.row.col.f32.tf32.tf32.f32 "
        "{%0,%1,%2,%3}, {%4,%5,%6,%7}, {%8,%9}, {%0,%1,%2,%3};"
        : "+f"(c[0]), "+f"(c[1]), "+f"(c[2]), "+f"(c[3])
        : "r"(a[0]), "r"(a[1]), "r"(a[2]), "r"(a[3]),
          "r"(b[0]), "r"(b[1]));
}
__device__ __forceinline__ void ldsm_x4(uint32_t* r, uint32_t addr) {
    asm volatile("ldmatrix.sync.aligned.m8n8.x4.shared.b16 {%0,%1,%2,%3}, [%4];"
        : "=r"(r[0]), "=r"(r[1]), "=r"(r[2]), "=r"(r[3]) : "r"(addr));
}

// ---------------------------------------------------------------------------
// Prep kernels
// ---------------------------------------------------------------------------
__global__ void cvt_x_kernel(const float* __restrict__ x)
{
    const long i = ((long)blockIdx.x * 256 + threadIdx.x) * 4;
    float4 v = *(const float4*)(x + i);
    uint4 u = make_uint4(cvt_tf32(v.x), cvt_tf32(v.y), cvt_tf32(v.z), cvt_tf32(v.w));
    *(uint4*)&g_xc[i] = u;
}

__global__ void transpose_tf32(const float* __restrict__ W, int K, int N, int which)
{
    __shared__ uint32_t t[32][33];
    uint32_t* WT = which ? g_woutT : g_wqkvT;
    const int nb = blockIdx.x * 32, kb = blockIdx.y * 32;
    const int tx = threadIdx.x, ty = threadIdx.y;
#pragma unroll
    for (int j = 0; j < 32; j += 8)
        t[ty + j][tx] = cvt_tf32(W[(long)(kb + ty + j) * N + nb + tx]);
    __syncthreads();
#pragma unroll
    for (int j = 0; j < 32; j += 8)
        WT[(long)(nb + ty + j) * K + kb + tx] = t[tx][ty + j];
}

// ---------------------------------------------------------------------------
// tf32 GEMM, ldmatrix + 3-stage cp.async, ONE barrier per K-iter.
// Block 128x128x32, 8 warps (2m x 4n), warp 64x32, K-major pitch-36 tiles.
// B-fragments loaded PAIRWISE via ldmatrix.x4 (16 n-rows per instruction):
// per k8-step 6 LDSM (4 A-x4 + 2 B-pair-x4) feed 16 mma.
// MODE 0: A = g_attn, float C = acc + bias.
// MODE 1: A = g_xc, scatter tf32(acc+bias) into g_q(/8)/g_k/g_v (B,H,S,HD).
// ---------------------------------------------------------------------------
#define BM 128
#define BN 128
#define BK 32
#define PITCH 36
#define TS_SZ (BM * PITCH)
#define STAGE_SZ (2 * TS_SZ)
#define NSTAGE 3
#define GEMM_SMEM_BYTES (NSTAGE * STAGE_SZ * 4)   // 110592 B -> 2 CTAs/SM

template <int MODE>
__global__ __launch_bounds__(256, 2) void gemm_ldsm(
    const float* __restrict__ bias, float* __restrict__ C,
    int M, int N, int K)
{
    extern __shared__ uint32_t smu[];
    const uint32_t sb = smem_u32(smu);

    const uint32_t* Au = (MODE == 0) ? g_attn : g_xc;
    const uint32_t* WT = (MODE == 0) ? g_woutT : g_wqkvT;

    const int tid = threadIdx.x;
    const int wid = tid >> 5;
    const int lane = tid & 31;
    const int g = lane >> 2;
    const int t4 = lane & 3;
    const int m0w = (wid >> 2) * 64;
    const int n0w = (wid & 3) * 32;
    const int bm = blockIdx.y * BM;
    const int bn = blockIdx.x * BN;

    // A x4: lanes 0-15 -> 16 rows @k0, lanes 16-31 -> 16 rows @k4
    const uint32_t a_off = ((m0w + (lane & 15)) * PITCH + (lane >> 4) * 4) * 4;
    // B pair-x4: lanes 0-7 rows n..n+7@k0, 8-15 @k4, 16-23 rows n+8..n+15@k0, 24-31 @k4
    const uint32_t bp_off =
        ((n0w + (lane & 7) + ((lane >> 4) & 1) * 8) * PITCH
         + ((lane >> 3) & 1) * 4) * 4;

    const int l_row = tid >> 3;
    const int l_kc  = (tid & 7) * 4;

    auto load_tile = [&](int it) {
        const int kb = it * BK;
        uint32_t dstA = sb + (it % NSTAGE) * STAGE_SZ * 4;
        uint32_t dstB = dstA + TS_SZ * 4;
#pragma unroll
        for (int c = 0; c < 4; ++c) {
            const int row = l_row + c * 32;
            cp_async16(dstA + (row * PITCH + l_kc) * 4,
                       Au + (long)(bm + row) * K + kb + l_kc);
            cp_async16(dstB + (row * PITCH + l_kc) * 4,
                       WT + (long)(bn + row) * K + kb + l_kc);
        }
        cp_commit();
    };

    float acc[4][4][4];
#pragma unroll
    for (int ma = 0; ma < 4; ++ma)
#pragma unroll
        for (int na = 0; na < 4; ++na)
#pragma unroll
            for (int i = 0; i < 4; ++i) acc[ma][na][i] = 0.f;

    const int NIT = K / BK;
    load_tile(0);
    load_tile(1);

    for (int it = 0; it < NIT; ++it) {
        cp_wait1();
        __syncthreads();
        if (it + 2 < NIT) load_tile(it + 2);

        const uint32_t abase = sb + (it % NSTAGE) * STAGE_SZ * 4 + a_off;
        const uint32_t bbase = sb + (it % NSTAGE) * STAGE_SZ * 4 + TS_SZ * 4 + bp_off;
#pragma unroll
        for (int ks = 0; ks < 4; ++ks) {
            const int kk = ks * 8;
            uint32_t af[4][4];
            uint32_t bq[2][4];           // bq[p] = frags for na=2p (r0,r1) and na=2p+1 (r2,r3)
#pragma unroll
            for (int ma = 0; ma < 4; ++ma)
                ldsm_x4(af[ma], abase + ma * (16 * PITCH * 4) + kk * 4);
#pragma unroll
            for (int p = 0; p < 2; ++p)
                ldsm_x4(bq[p], bbase + p * (16 * PITCH * 4) + kk * 4);
#pragma unroll
            for (int ma = 0; ma < 4; ++ma)
#pragma unroll
                for (int p = 0; p < 2; ++p) {
                    mma_tf32(acc[ma][2 * p],     af[ma], &bq[p][0]);
                    mma_tf32(acc[ma][2 * p + 1], af[ma], &bq[p][2]);
                }
        }
    }

    // --- epilogue ------------------------------------------------------------
#pragma unroll
    for (int na = 0; na < 4; ++na) {
        const int col = bn + n0w + na * 8 + 2 * t4;
        const float2 bx = *(const float2*)&bias[col];

        if (MODE == 0) {
#pragma unroll
            for (int ma = 0; ma < 4; ++ma) {
                const long r0 = bm + m0w + ma * 16 + g;
                *(float2*)&C[r0 * N + col] =
                    make_float2(acc[ma][na][0] + bx.x, acc[ma][na][1] + bx.y);
                *(float2*)&C[(r0 + 8) * N + col] =
                    make_float2(acc[ma][na][2] + bx.x, acc[ma][na][3] + bx.y);
            }
        } else {
            const int h = col / 192;
            const int rem = col - h * 192;
            const int which = rem >> 6;
            const int d = rem & 63;
            uint32_t* dst = (which == 0) ? g_q : (which == 1) ? g_k : g_v;
            const float sc = (which == 0) ? 0.125f : 1.0f;
#pragma unroll
            for (int ma = 0; ma < 4; ++ma) {
                const int m = bm + m0w + ma * 16 + g;
                const int b = m >> 11;
                const int s = m & (S_ - 1);
                const long base = (((long)(b * H_ + h)) * S_ + s) * HD_ + d;
                uint2 o0 = make_uint2(cvt_tf32((acc[ma][na][0] + bx.x) * sc),
                                      cvt_tf32((acc[ma][na][1] + bx.y) * sc));
                uint2 o1 = make_uint2(cvt_tf32((acc[ma][na][2] + bx.x) * sc),
                                      cvt_tf32((acc[ma][na][3] + bx.y) * sc));
                *(uint2*)&dst[base] = o0;
                *(uint2*)&dst[base + 8 * HD_] = o1;
            }
        }
    }
}

// ---------------------------------------------------------------------------
// Flash attention: ldmatrix (pair-x4 B-frags) + in-register online softmax.
// Per k8-step each phase issues 5 LDSM (1 x4 + 4 pair-x4) for 8 mma.
// Only ceil(vlen/64) key tiles (exp underflow vs -1e6 mask is exactly 0).
// ---------------------------------------------------------------------------
#define QT 128
#define AP 68
#define QS_OFF   0
#define KS_OFF   (QT * AP)
#define VS_OFF   (KS_OFF + 64 * AP)
#define SS_OFF   (VS_OFF + 64 * AP)
#define ATTN_SMEM_BYTES ((SS_OFF + QT * AP) * 4)   // 104448 B

__global__ __launch_bounds__(256, 2) void attn_tc(const int* __restrict__ val_lens)
{
    extern __shared__ uint32_t sm[];
    uint32_t* Ks  = sm + KS_OFF;         // [kk][d]
    uint32_t* VsT = sm + VS_OFF;         // [d][kk]
    uint32_t* Ssu = sm + SS_OFF;         // [q][kk] tf32 probs (warp-private rows)
    uint32_t* Qs  = sm + QS_OFF;         // [q][d]

    const int q0 = blockIdx.x * QT;
    const int h  = blockIdx.y;
    const int b  = blockIdx.z;
    const int vlen = val_lens[b];
    const int tid = threadIdx.x;
    const int wid = tid >> 5;
    const int lane = tid & 31;
    const int g = lane >> 2;
    const int t4 = lane & 3;
    const int m0 = wid * 16;

    const long headoff = ((long)(b * H_ + h)) * S_ * HD_;
    const uint32_t* qbase = g_q + headoff;
    const uint32_t* kbase = g_k + headoff;
    const uint32_t* vbase = g_v + headoff;

    const uint32_t sb = smem_u32(sm);
    const uint32_t qa_off = ((m0 + (lane & 15)) * AP + (lane >> 4) * 4) * 4;
    // pair-x4 offset for B-side tiles (16 rows per instruction)
    const uint32_t nbp_off =
        (((lane & 7) + ((lane >> 4) & 1) * 8) * AP + ((lane >> 3) & 1) * 4) * 4;
    const uint32_t QS_B = sb + QS_OFF * 4;
    const uint32_t KS_B = sb + KS_OFF * 4;
    const uint32_t VS_B = sb + VS_OFF * 4;
    const uint32_t SS_B = sb + SS_OFF * 4;

    // Load Q tile (tf32 patterns, pre-scaled)
    {
        const int r = tid >> 1;
        const int c0 = (tid & 1) * 32;
        const uint32_t* src = qbase + (long)(q0 + r) * HD_ + c0;
        uint32_t* dst = &Qs[r * AP + c0];
#pragma unroll
        for (int j = 0; j < 32; j += 4)
            *(uint4*)(dst + j) = *(const uint4*)(src + j);
    }

    float m_lo = -3.0e38f, m_hi = -3.0e38f;
    float l_lo = 0.f, l_hi = 0.f;
    float acc_o[8][4];
#pragma unroll
    for (int na = 0; na < 8; ++na)
#pragma unroll
        for (int i = 0; i < 4; ++i) acc_o[na][i] = 0.f;

    const int ntiles = (vlen + 63) >> 6;
    for (int kt = 0; kt < ntiles; ++kt) {
        // --- K tile via cp.async; V transposed via registers (overlapped) ---
#pragma unroll
        for (int c = 0; c < 4; ++c) {
            const int id = tid + c * 256;
            const int r = id >> 4;
            const int dc = (id & 15) * 4;
            cp_async16(KS_B + (r * AP + dc) * 4,
                       kbase + (long)(kt * 64 + r) * HD_ + dc);
        }
        cp_commit();
        {
            const int vr = tid >> 2;
            const int vd0 = (tid & 3) * 16;
            const uint32_t* src = vbase + (long)(kt * 64 + vr) * HD_ + vd0;
#pragma unroll
            for (int j = 0; j < 16; j += 4) {
                uint4 v = *(const uint4*)(src + j);
                VsT[(vd0 + j + 0) * AP + vr] = v.x;
                VsT[(vd0 + j + 1) * AP + vr] = v.y;
                VsT[(vd0 + j + 2) * AP + vr] = v.z;
                VsT[(vd0 + j + 3) * AP + vr] = v.w;
            }
        }
        cp_wait0();
        __syncthreads();

        // --- Phase A: S = Q K^T (x4 + pair-x4 LDSM, mma) ---
        float accs[8][4];
#pragma unroll
        for (int na = 0; na < 8; ++na)
#pragma unroll
            for (int i = 0; i < 4; ++i) accs[na][i] = 0.f;
#pragma unroll
        for (int kk = 0; kk < 64; kk += 8) {
            uint32_t af[4];
            ldsm_x4(af, QS_B + qa_off + kk * 4);
#pragma unroll
            for (int p = 0; p < 4; ++p) {
                uint32_t bq[4];
                ldsm_x4(bq, KS_B + nbp_off + p * (16 * AP * 4) + kk * 4);
                mma_tf32(accs[2 * p],     af, &bq[0]);
                mma_tf32(accs[2 * p + 1], af, &bq[2]);
            }
        }

        {   // masked row max (quad shfl reduction)
            const int cbase = kt * 64 + 2 * t4;
            float mx_lo = -3.0e38f, mx_hi = -3.0e38f;
#pragma unroll
            for (int na = 0; na < 8; ++na) {
                const int c0 = cbase + na * 8;
                if (c0 < vlen)     { mx_lo = fmaxf(mx_lo, accs[na][0]);
                                     mx_hi = fmaxf(mx_hi, accs[na][2]); }
                if (c0 + 1 < vlen) { mx_lo = fmaxf(mx_lo, accs[na][1]);
                                     mx_hi = fmaxf(mx_hi, accs[na][3]); }
            }
            mx_lo = fmaxf(mx_lo, __shfl_xor_sync(0xffffffffu, mx_lo, 1));
            mx_lo = fmaxf(mx_lo, __shfl_xor_sync(0xffffffffu, mx_lo, 2));
            mx_hi = fmaxf(mx_hi, __shfl_xor_sync(0xffffffffu, mx_hi, 1));
            mx_hi = fmaxf(mx_hi, __shfl_xor_sync(0xffffffffu, mx_hi, 2));

            const float mn_lo = fmaxf(m_lo, mx_lo);
            const float mn_hi = fmaxf(m_hi, mx_hi);
            const float al_lo = __expf(m_lo - mn_lo);
            const float al_hi = __expf(m_hi - mn_hi);

            float s_lo = 0.f, s_hi = 0.f;
#pragma unroll
            for (int na = 0; na < 8; ++na) {
                const int c0 = cbase + na * 8;
                const float p0 = (c0 < vlen)     ? __expf(accs[na][0] - mn_lo) : 0.f;
                const float p1 = (c0 + 1 < vlen) ? __expf(accs[na][1] - mn_lo) : 0.f;
                const float p2 = (c0 < vlen)     ? __expf(accs[na][2] - mn_hi) : 0.f;
                const float p3 = (c0 + 1 < vlen) ? __expf(accs[na][3] - mn_hi) : 0.f;
                s_lo += p0 + p1;
                s_hi += p2 + p3;
                *(uint2*)&Ssu[(m0 + g) * AP + na * 8 + 2 * t4] =
                    make_uint2(cvt_tf32(p0), cvt_tf32(p1));
                *(uint2*)&Ssu[(m0 + g + 8) * AP + na * 8 + 2 * t4] =
                    make_uint2(cvt_tf32(p2), cvt_tf32(p3));
            }
            s_lo += __shfl_xor_sync(0xffffffffu, s_lo, 1);
            s_lo += __shfl_xor_sync(0xffffffffu, s_lo, 2);
            s_hi += __shfl_xor_sync(0xffffffffu, s_hi, 1);
            s_hi += __shfl_xor_sync(0xffffffffu, s_hi, 2);

            l_lo = l_lo * al_lo + s_lo;
            l_hi = l_hi * al_hi + s_hi;
            m_lo = mn_lo;
            m_hi = mn_hi;

#pragma unroll
            for (int na = 0; na < 8; ++na) {
                acc_o[na][0] *= al_lo; acc_o[na][1] *= al_lo;
                acc_o[na][2] *= al_hi; acc_o[na][3] *= al_hi;
            }
        }
        __syncwarp();   // Ssu rows are warp-private; make lane STS visible to LDSM

        // --- Phase C: O += P * V (x4 + pair-x4 LDSM, mma) ---
#pragma unroll
        for (int kk = 0; kk < 64; kk += 8) {
            uint32_t af[4];
            ldsm_x4(af, SS_B + qa_off + kk * 4);
#pragma unroll
            for (int p = 0; p < 4; ++p) {
                uint32_t bq[4];
                ldsm_x4(bq, VS_B + nbp_off + p * (16 * AP * 4) + kk * 4);
                mma_tf32(acc_o[2 * p],     af, &bq[0]);
                mma_tf32(acc_o[2 * p + 1], af, &bq[2]);
            }
        }
        __syncthreads();   // protect Ks/VsT before next tile's loads
    }

    // --- epilogue: normalize, write g_attn as tf32 patterns (B,S,D) ---
    {
        const float li_lo = 1.0f / l_lo;
        const float li_hi = 1.0f / l_hi;
        const long r0 = (long)b * S_ + q0 + m0 + g;
#pragma unroll
        for (int na = 0; na < 8; ++na) {
            const int col = h * HD_ + na * 8 + 2 * t4;
            *(uint2*)&g_attn[r0 * D_ + col] =
                make_uint2(cvt_tf32(acc_o[na][0] * li_lo),
                           cvt_tf32(acc_o[na][1] * li_lo));
            *(uint2*)&g_attn[(r0 + 8) * D_ + col] =
                make_uint2(cvt_tf32(acc_o[na][2] * li_hi),
                           cvt_tf32(acc_o[na][3] * li_hi));
        }
    }
}

// ---------------------------------------------------------------------------
// Host launcher (graph-capturable: kernel launches only, no allocs/syncs)
// ---------------------------------------------------------------------------
extern "C" void kernel_launch(void* const* d_in, const int* in_sizes, int n_in,
                              void* d_out, int out_size)
{
    const float* x        = (const float*)d_in[0];
    const float* Wqkv     = (const float*)d_in[1];
    const float* bqkv     = (const float*)d_in[2];
    const float* Wout     = (const float*)d_in[3];
    const float* bout     = (const float*)d_in[4];
    const int*   val_lens = (const int*)d_in[5];
    float* out = (float*)d_out;

    cudaFuncSetAttribute(gemm_ldsm<1>,
                         cudaFuncAttributeMaxDynamicSharedMemorySize, GEMM_SMEM_BYTES);
    cudaFuncSetAttribute(gemm_ldsm<0>,
                         cudaFuncAttributeMaxDynamicSharedMemorySize, GEMM_SMEM_BYTES);
    cudaFuncSetAttribute(attn_tc,
                         cudaFuncAttributeMaxDynamicSharedMemorySize, ATTN_SMEM_BYTES);

    // 0) Prep: tf32-pattern conversions/transposes
    cvt_x_kernel<<<(B_ * S_ * D_) / (256 * 4), 256>>>(x);
    {
        dim3 blk(32, 8);
        transpose_tf32<<<dim3((3 * D_) / 32, D_ / 32), blk>>>(Wqkv, D_, 3 * D_, 0);
        transpose_tf32<<<dim3(D_ / 32, D_ / 32), blk>>>(Wout, D_, D_, 1);
    }
    // 1) QKV projection -> tf32-pattern Q/K/V in (B,H,S,HD)
    {
        dim3 grid((3 * D_) / BN, (B_ * S_) / BM);   // 24 x 64
        gemm_ldsm<1><<<grid, 256, GEMM_SMEM_BYTES>>>(bqkv, nullptr, B_ * S_, 3 * D_, D_);
    }
    // 2) Flash attention -> g_attn (tf32 patterns)
    {
        dim3 grid(S_ / QT, H_, B_);                 // 16 x 16 x 4
        attn_tc<<<grid, 256, ATTN_SMEM_BYTES>>>(val_lens);
    }
    // 3) Output projection -> d_out (fp32 + bias)
    {
        dim3 grid(D_ / BN, (B_ * S_) / BM);         // 8 x 64
        gemm_ldsm<0><<<grid, 256, GEMM_SMEM_BYTES>>>(bout, out, B_ * S_, D_, D_);
    }
}

// round 12
// speedup vs baseline: 2.1585x; 1.6592x over previous
#include <cuda_runtime.h>
#include <cuda_fp16.h>
#include <cstdint>

#define B_ 4
#define S_ 2048
#define D_ 1024
#define H_ 16
#define HD_ 64

// ---------------------------------------------------------------------------
// Scratch (device globals; all tensor-core operands are fp16)
// ---------------------------------------------------------------------------
__device__ __half g_q[B_ * H_ * S_ * HD_];     // Q pre-scaled by 1/8
__device__ __half g_k[B_ * H_ * S_ * HD_];
__device__ __half g_v[B_ * H_ * S_ * HD_];
__device__ __half g_attn[B_ * S_ * D_];
__device__ __half g_xc[B_ * S_ * D_];          // half(x)
__device__ __half g_wqkvT[3 * D_ * D_];        // W^T (K-major)
__device__ __half g_woutT[D_ * D_];

// ---------------------------------------------------------------------------
// PTX helpers
// ---------------------------------------------------------------------------
__device__ __forceinline__ uint32_t smem_u32(const void* p) {
    return (uint32_t)__cvta_generic_to_shared(p);
}
__device__ __forceinline__ void cp_async16(uint32_t dst, const void* src) {
    asm volatile("cp.async.cg.shared.global [%0], [%1], 16;" :: "r"(dst), "l"(src));
}
__device__ __forceinline__ void cp_commit() {
    asm volatile("cp.async.commit_group;" ::: "memory");
}
__device__ __forceinline__ void cp_wait1() {
    asm volatile("cp.async.wait_group 1;" ::: "memory");
}
__device__ __forceinline__ void cp_wait0() {
    asm volatile("cp.async.wait_group 0;" ::: "memory");
}
// fp16 mma, fp32 accumulate: m16n8k16
__device__ __forceinline__ void mma_f16(float* c, const uint32_t* a, const uint32_t* b) {
    asm("mma.sync.aligned.m16n8k16.row.col.f32.f16.f16.f32 "
        "{%0,%1,%2,%3}, {%4,%5,%6,%7}, {%8,%9}, {%0,%1,%2,%3};"
        : "+f"(c[0]), "+f"(c[1]), "+f"(c[2]), "+f"(c[3])
        : "r"(a[0]), "r"(a[1]), "r"(a[2]), "r"(a[3]),
          "r"(b[0]), "r"(b[1]));
}
__device__ __forceinline__ void ldsm_x4(uint32_t* r, uint32_t addr) {
    asm volatile("ldmatrix.sync.aligned.m8n8.x4.shared.b16 {%0,%1,%2,%3}, [%4];"
        : "=r"(r[0]), "=r"(r[1]), "=r"(r[2]), "=r"(r[3]) : "r"(addr));
}

// ---------------------------------------------------------------------------
// Prep kernels: x -> half; W -> transposed half (K-major)
// ---------------------------------------------------------------------------
__global__ void cvt_x_kernel(const float* __restrict__ x)
{
    const long i = ((long)blockIdx.x * 256 + threadIdx.x) * 8;
    float4 v0 = *(const float4*)(x + i);
    float4 v1 = *(const float4*)(x + i + 4);
    __half2 h0 = __floats2half2_rn(v0.x, v0.y);
    __half2 h1 = __floats2half2_rn(v0.z, v0.w);
    __half2 h2 = __floats2half2_rn(v1.x, v1.y);
    __half2 h3 = __floats2half2_rn(v1.z, v1.w);
    uint4 u = make_uint4(*(uint32_t*)&h0, *(uint32_t*)&h1,
                         *(uint32_t*)&h2, *(uint32_t*)&h3);
    *(uint4*)&g_xc[i] = u;
}

__global__ void transpose_h(const float* __restrict__ W, int K, int N, int which)
{
    __shared__ __half t[32][33];
    __half* WT = which ? g_woutT : g_wqkvT;
    const int nb = blockIdx.x * 32, kb = blockIdx.y * 32;
    const int tx = threadIdx.x, ty = threadIdx.y;
#pragma unroll
    for (int j = 0; j < 32; j += 8)
        t[ty + j][tx] = __float2half_rn(W[(long)(kb + ty + j) * N + nb + tx]);
    __syncthreads();
#pragma unroll
    for (int j = 0; j < 32; j += 8)
        WT[(long)(nb + ty + j) * K + kb + tx] = t[tx][ty + j];
}

// ---------------------------------------------------------------------------
// fp16 GEMM: C[M,N] = A @ W + bias. Block 128x128x32, 8 warps (2m x 4n),
// warp 64x32, m16n8k16. K-major half tiles, pitch 40 halves (80 B rows,
// LDSM bank stride 20 -> conflict-free). 3-stage cp.async, 1 barrier/iter.
// Per BK=32 iter: 2 k16-steps x (6 LDSM + 16 mma).
// MODE 0: A = g_attn, fp32 C = acc + bias.
// MODE 1: A = g_xc, scatter half(acc+bias) into g_q(*1/8)/g_k/g_v (B,H,S,HD).
// ---------------------------------------------------------------------------
#define BM 128
#define BN 128
#define BK 32
#define PITCHB 80                        // bytes per smem row (40 halves)
#define TS_B (BM * PITCHB)               // 10240 B per operand tile
#define STAGE_B (2 * TS_B)               // 20480 B
#define NSTAGE 3
#define GEMM_SMEM_BYTES (NSTAGE * STAGE_B)   // 61440 B -> 2 CTAs/SM easily

template <int MODE>
__global__ __launch_bounds__(256, 2) void gemm_h(
    const float* __restrict__ bias, float* __restrict__ C,
    int M, int N, int K)
{
    extern __shared__ char smc[];
    const uint32_t sb = smem_u32(smc);

    const __half* Au = (MODE == 0) ? g_attn : g_xc;
    const __half* WT = (MODE == 0) ? g_woutT : g_wqkvT;

    const int tid = threadIdx.x;
    const int wid = tid >> 5;
    const int lane = tid & 31;
    const int g = lane >> 2;
    const int t4 = lane & 3;
    const int m0w = (wid >> 2) * 64;
    const int n0w = (wid & 3) * 32;
    const int bm = blockIdx.y * BM;
    const int bn = blockIdx.x * BN;

    // A x4: rows m0+(lane&15); 16B unit selects k-halves 0-7 / 8-15
    const uint32_t a_off = (m0w + (lane & 15)) * PITCHB + (lane >> 4) * 16;
    // B pair-x4: rows n0w+(lane&7)+((lane>>4)&1)*8; ((lane>>3)&1) selects k 16B
    const uint32_t bp_off =
        (n0w + (lane & 7) + ((lane >> 4) & 1) * 8) * PITCHB
        + ((lane >> 3) & 1) * 16;

    // loaders: 512 16B chunks per operand (4 per row of 64B), 2 per thread
    auto load_tile = [&](int it) {
        const int kb = it * BK;
        const uint32_t dstA = sb + (it % NSTAGE) * STAGE_B;
        const uint32_t dstB = dstA + TS_B;
#pragma unroll
        for (int c = 0; c < 2; ++c) {
            const int id = tid + c * 256;
            const int row = id >> 2;
            const int kc = id & 3;                 // 16B unit (8 halves)
            cp_async16(dstA + row * PITCHB + kc * 16,
                       Au + (long)(bm + row) * K + kb + kc * 8);
            cp_async16(dstB + row * PITCHB + kc * 16,
                       WT + (long)(bn + row) * K + kb + kc * 8);
        }
        cp_commit();
    };

    float acc[4][4][4];
#pragma unroll
    for (int ma = 0; ma < 4; ++ma)
#pragma unroll
        for (int na = 0; na < 4; ++na)
#pragma unroll
            for (int i = 0; i < 4; ++i) acc[ma][na][i] = 0.f;

    const int NIT = K / BK;
    load_tile(0);
    load_tile(1);

    for (int it = 0; it < NIT; ++it) {
        cp_wait1();
        __syncthreads();
        if (it + 2 < NIT) load_tile(it + 2);

        const uint32_t abase = sb + (it % NSTAGE) * STAGE_B + a_off;
        const uint32_t bbase = sb + (it % NSTAGE) * STAGE_B + TS_B + bp_off;
#pragma unroll
        for (int ks = 0; ks < 2; ++ks) {           // k16 steps
            const int kB = ks * 32;                // 16 halves = 32 bytes
            uint32_t af[4][4];
            uint32_t bq[2][4];
#pragma unroll
            for (int ma = 0; ma < 4; ++ma)
                ldsm_x4(af[ma], abase + ma * (16 * PITCHB) + kB);
#pragma unroll
            for (int p = 0; p < 2; ++p)
                ldsm_x4(bq[p], bbase + p * (16 * PITCHB) + kB);
#pragma unroll
            for (int ma = 0; ma < 4; ++ma)
#pragma unroll
                for (int p = 0; p < 2; ++p) {
                    mma_f16(acc[ma][2 * p],     af[ma], &bq[p][0]);
                    mma_f16(acc[ma][2 * p + 1], af[ma], &bq[p][2]);
                }
        }
    }

    // --- epilogue ------------------------------------------------------------
#pragma unroll
    for (int na = 0; na < 4; ++na) {
        const int col = bn + n0w + na * 8 + 2 * t4;
        const float2 bx = *(const float2*)&bias[col];

        if (MODE == 0) {
#pragma unroll
            for (int ma = 0; ma < 4; ++ma) {
                const long r0 = bm + m0w + ma * 16 + g;
                *(float2*)&C[r0 * N + col] =
                    make_float2(acc[ma][na][0] + bx.x, acc[ma][na][1] + bx.y);
                *(float2*)&C[(r0 + 8) * N + col] =
                    make_float2(acc[ma][na][2] + bx.x, acc[ma][na][3] + bx.y);
            }
        } else {
            const int h = col / 192;
            const int rem = col - h * 192;
            const int which = rem >> 6;
            const int d = rem & 63;
            __half* dst = (which == 0) ? g_q : (which == 1) ? g_k : g_v;
            const float sc = (which == 0) ? 0.125f : 1.0f;
#pragma unroll
            for (int ma = 0; ma < 4; ++ma) {
                const int m = bm + m0w + ma * 16 + g;
                const int b = m >> 11;
                const int s = m & (S_ - 1);
                const long base = (((long)(b * H_ + h)) * S_ + s) * HD_ + d;
                *(__half2*)&dst[base] =
                    __floats2half2_rn((acc[ma][na][0] + bx.x) * sc,
                                      (acc[ma][na][1] + bx.y) * sc);
                *(__half2*)&dst[base + 8 * HD_] =
                    __floats2half2_rn((acc[ma][na][2] + bx.x) * sc,
                                      (acc[ma][na][3] + bx.y) * sc);
            }
        }
    }
}

// ---------------------------------------------------------------------------
// fp16 flash attention: ldmatrix (pair-x4) + in-register online softmax.
// Tiles: Q[128][64], K[64][64], V^T[64][64], P[128][64] halves, pitch 72
// (144 B rows, LDSM bank stride 36 -> conflict-free). Per phase per k16:
// 5 LDSM + 8 mma (4 steps instead of tf32's 8).
// Grid is batch-fastest to balance vlen skew across waves.
// Only ceil(vlen/64) key tiles (exp underflow vs -1e6 mask is exactly 0).
// ---------------------------------------------------------------------------
#define QT 128
#define APH 72
#define APB (APH * 2)                    // 144 bytes/row
#define QS_B_OFF 0
#define KS_B_OFF (QT * APB)              // 18432
#define VS_B_OFF (KS_B_OFF + 64 * APB)   // +9216
#define SS_B_OFF (VS_B_OFF + 64 * APB)   // +9216
#define ATTN_SMEM_BYTES (SS_B_OFF + QT * APB)   // 55296 B

__global__ __launch_bounds__(256, 2) void attn_h(const int* __restrict__ val_lens)
{
    extern __shared__ char smc[];
    __half* Qs  = (__half*)(smc + QS_B_OFF);
    __half* Ks  = (__half*)(smc + KS_B_OFF);
    __half* VsT = (__half*)(smc + VS_B_OFF);
    __half* Ss  = (__half*)(smc + SS_B_OFF);

    const int b  = blockIdx.x;           // batch fastest -> balanced waves
    const int h  = blockIdx.y;
    const int q0 = blockIdx.z * QT;
    const int vlen = val_lens[b];
    const int tid = threadIdx.x;
    const int wid = tid >> 5;
    const int lane = tid & 31;
    const int g = lane >> 2;
    const int t4 = lane & 3;
    const int m0 = wid * 16;

    const long headoff = ((long)(b * H_ + h)) * S_ * HD_;
    const __half* qbase = g_q + headoff;
    const __half* kbase = g_k + headoff;
    const __half* vbase = g_v + headoff;

    const uint32_t sb = smem_u32(smc);
    const uint32_t qa_off = (m0 + (lane & 15)) * APB + (lane >> 4) * 16;
    const uint32_t nbp_off =
        ((lane & 7) + ((lane >> 4) & 1) * 8) * APB + ((lane >> 3) & 1) * 16;
    const uint32_t QS_B = sb + QS_B_OFF;
    const uint32_t KS_B = sb + KS_B_OFF;
    const uint32_t VS_B = sb + VS_B_OFF;
    const uint32_t SS_B = sb + SS_B_OFF;

    // Load Q tile (half, pre-scaled): 32 halves per thread
    {
        const int r = tid >> 1;
        const int c0 = (tid & 1) * 32;
        const __half* src = qbase + (long)(q0 + r) * HD_ + c0;
        __half* dst = &Qs[r * APH + c0];
#pragma unroll
        for (int j = 0; j < 32; j += 8)
            *(uint4*)(dst + j) = *(const uint4*)(src + j);
    }

    float m_lo = -3.0e38f, m_hi = -3.0e38f;
    float l_lo = 0.f, l_hi = 0.f;
    float acc_o[8][4];
#pragma unroll
    for (int na = 0; na < 8; ++na)
#pragma unroll
        for (int i = 0; i < 4; ++i) acc_o[na][i] = 0.f;

    const int ntiles = (vlen + 63) >> 6;
    for (int kt = 0; kt < ntiles; ++kt) {
        // --- K tile via cp.async (64 rows x 128B = 512 chunks, 2/thread) ---
#pragma unroll
        for (int c = 0; c < 2; ++c) {
            const int id = tid + c * 256;
            const int r = id >> 3;
            const int dc = id & 7;                 // 16B unit
            cp_async16(KS_B + r * APB + dc * 16,
                       kbase + (long)(kt * 64 + r) * HD_ + dc * 8);
        }
        cp_commit();
        // --- V tile transposed: 16 halves per thread, scattered stores ---
        {
            const int vr = tid >> 2;
            const int vd0 = (tid & 3) * 16;
            const __half* src = vbase + (long)(kt * 64 + vr) * HD_ + vd0;
            __half tmp[16];
            *(uint4*)&tmp[0] = *(const uint4*)(src);
            *(uint4*)&tmp[8] = *(const uint4*)(src + 8);
#pragma unroll
            for (int j = 0; j < 16; ++j)
                VsT[(vd0 + j) * APH + vr] = tmp[j];
        }
        cp_wait0();
        __syncthreads();

        // --- Phase A: S = Q K^T ---
        float accs[8][4];
#pragma unroll
        for (int na = 0; na < 8; ++na)
#pragma unroll
            for (int i = 0; i < 4; ++i) accs[na][i] = 0.f;
#pragma unroll
        for (int ks = 0; ks < 4; ++ks) {           // k16 steps over HD=64
            const int kB = ks * 32;
            uint32_t af[4];
            ldsm_x4(af, QS_B + qa_off + kB);
#pragma unroll
            for (int p = 0; p < 4; ++p) {
                uint32_t bq[4];
                ldsm_x4(bq, KS_B + nbp_off + p * (16 * APB) + kB);
                mma_f16(accs[2 * p],     af, &bq[0]);
                mma_f16(accs[2 * p + 1], af, &bq[2]);
            }
        }

        {   // in-register masked online softmax (quad shfl reductions)
            const int cbase = kt * 64 + 2 * t4;
            float mx_lo = -3.0e38f, mx_hi = -3.0e38f;
#pragma unroll
            for (int na = 0; na < 8; ++na) {
                const int c0 = cbase + na * 8;
                if (c0 < vlen)     { mx_lo = fmaxf(mx_lo, accs[na][0]);
                                     mx_hi = fmaxf(mx_hi, accs[na][2]); }
                if (c0 + 1 < vlen) { mx_lo = fmaxf(mx_lo, accs[na][1]);
                                     mx_hi = fmaxf(mx_hi, accs[na][3]); }
            }
            mx_lo = fmaxf(mx_lo, __shfl_xor_sync(0xffffffffu, mx_lo, 1));
            mx_lo = fmaxf(mx_lo, __shfl_xor_sync(0xffffffffu, mx_lo, 2));
            mx_hi = fmaxf(mx_hi, __shfl_xor_sync(0xffffffffu, mx_hi, 1));
            mx_hi = fmaxf(mx_hi, __shfl_xor_sync(0xffffffffu, mx_hi, 2));

            const float mn_lo = fmaxf(m_lo, mx_lo);
            const float mn_hi = fmaxf(m_hi, mx_hi);
            const float al_lo = __expf(m_lo - mn_lo);
            const float al_hi = __expf(m_hi - mn_hi);

            float s_lo = 0.f, s_hi = 0.f;
#pragma unroll
            for (int na = 0; na < 8; ++na) {
                const int c0 = cbase + na * 8;
                const float p0 = (c0 < vlen)     ? __expf(accs[na][0] - mn_lo) : 0.f;
                const float p1 = (c0 + 1 < vlen) ? __expf(accs[na][1] - mn_lo) : 0.f;
                const float p2 = (c0 < vlen)     ? __expf(accs[na][2] - mn_hi) : 0.f;
                const float p3 = (c0 + 1 < vlen) ? __expf(accs[na][3] - mn_hi) : 0.f;
                s_lo += p0 + p1;
                s_hi += p2 + p3;
                *(__half2*)&Ss[(m0 + g) * APH + na * 8 + 2 * t4] =
                    __floats2half2_rn(p0, p1);
                *(__half2*)&Ss[(m0 + g + 8) * APH + na * 8 + 2 * t4] =
                    __floats2half2_rn(p2, p3);
            }
            s_lo += __shfl_xor_sync(0xffffffffu, s_lo, 1);
            s_lo += __shfl_xor_sync(0xffffffffu, s_lo, 2);
            s_hi += __shfl_xor_sync(0xffffffffu, s_hi, 1);
            s_hi += __shfl_xor_sync(0xffffffffu, s_hi, 2);

            l_lo = l_lo * al_lo + s_lo;
            l_hi = l_hi * al_hi + s_hi;
            m_lo = mn_lo;
            m_hi = mn_hi;

#pragma unroll
            for (int na = 0; na < 8; ++na) {
                acc_o[na][0] *= al_lo; acc_o[na][1] *= al_lo;
                acc_o[na][2] *= al_hi; acc_o[na][3] *= al_hi;
            }
        }
        __syncwarp();   // Ss rows are warp-private; make STS visible to LDSM

        // --- Phase C: O += P V ---
#pragma unroll
        for (int ks = 0; ks < 4; ++ks) {
            const int kB = ks * 32;
            uint32_t af[4];
            ldsm_x4(af, SS_B + qa_off + kB);
#pragma unroll
            for (int p = 0; p < 4; ++p) {
                uint32_t bq[4];
                ldsm_x4(bq, VS_B + nbp_off + p * (16 * APB) + kB);
                mma_f16(acc_o[2 * p],     af, &bq[0]);
                mma_f16(acc_o[2 * p + 1], af, &bq[2]);
            }
        }
        __syncthreads();   // protect Ks/VsT before next tile's loads
    }

    // --- epilogue: normalize, write g_attn (half, B,S,D) ---
    {
        const float li_lo = 1.0f / l_lo;
        const float li_hi = 1.0f / l_hi;
        const long r0 = (long)b * S_ + q0 + m0 + g;
#pragma unroll
        for (int na = 0; na < 8; ++na) {
            const int col = h * HD_ + na * 8 + 2 * t4;
            *(__half2*)&g_attn[r0 * D_ + col] =
                __floats2half2_rn(acc_o[na][0] * li_lo, acc_o[na][1] * li_lo);
            *(__half2*)&g_attn[(r0 + 8) * D_ + col] =
                __floats2half2_rn(acc_o[na][2] * li_hi, acc_o[na][3] * li_hi);
        }
    }
}

// ---------------------------------------------------------------------------
// Host launcher (graph-capturable: kernel launches only, no allocs/syncs)
// ---------------------------------------------------------------------------
extern "C" void kernel_launch(void* const* d_in, const int* in_sizes, int n_in,
                              void* d_out, int out_size)
{
    const float* x        = (const float*)d_in[0];
    const float* Wqkv     = (const float*)d_in[1];
    const float* bqkv     = (const float*)d_in[2];
    const float* Wout     = (const float*)d_in[3];
    const float* bout     = (const float*)d_in[4];
    const int*   val_lens = (const int*)d_in[5];
    float* out = (float*)d_out;

    cudaFuncSetAttribute(gemm_h<1>,
                         cudaFuncAttributeMaxDynamicSharedMemorySize, GEMM_SMEM_BYTES);
    cudaFuncSetAttribute(gemm_h<0>,
                         cudaFuncAttributeMaxDynamicSharedMemorySize, GEMM_SMEM_BYTES);
    cudaFuncSetAttribute(attn_h,
                         cudaFuncAttributeMaxDynamicSharedMemorySize, ATTN_SMEM_BYTES);

    // 0) Prep: fp16 conversions/transposes
    cvt_x_kernel<<<(B_ * S_ * D_) / (256 * 8), 256>>>(x);
    {
        dim3 blk(32, 8);
        transpose_h<<<dim3((3 * D_) / 32, D_ / 32), blk>>>(Wqkv, D_, 3 * D_, 0);
        transpose_h<<<dim3(D_ / 32, D_ / 32), blk>>>(Wout, D_, D_, 1);
    }
    // 1) QKV projection -> half Q/K/V in (B,H,S,HD)
    {
        dim3 grid((3 * D_) / BN, (B_ * S_) / BM);   // 24 x 64
        gemm_h<1><<<grid, 256, GEMM_SMEM_BYTES>>>(bqkv, nullptr, B_ * S_, 3 * D_, D_);
    }
    // 2) Flash attention -> g_attn (half)
    {
        dim3 grid(B_, H_, S_ / QT);                 // batch-fastest
        attn_h<<<grid, 256, ATTN_SMEM_BYTES>>>(val_lens);
    }
    // 3) Output projection -> d_out (fp32 + bias)
    {
        dim3 grid(D_ / BN, (B_ * S_) / BM);         // 8 x 64
        gemm_h<0><<<grid, 256, GEMM_SMEM_BYTES>>>(bout, out, B_ * S_, D_, D_);
    }
}

// round 14
// speedup vs baseline: 2.3446x; 1.0862x over previous
#include <cuda_runtime.h>
#include <cuda_fp16.h>
#include <cstdint>

#define B_ 4
#define S_ 2048
#define D_ 1024
#define H_ 16
#define HD_ 64

// ---------------------------------------------------------------------------
// Scratch (device globals; all tensor-core operands are fp16)
// ---------------------------------------------------------------------------
__device__ __half g_q[B_ * H_ * S_ * HD_];     // Q pre-scaled by 1/8
__device__ __half g_k[B_ * H_ * S_ * HD_];
__device__ __half g_v[B_ * H_ * S_ * HD_];
__device__ __half g_attn[B_ * S_ * D_];
__device__ __half g_xc[B_ * S_ * D_];          // half(x)
__device__ __half g_wqkvT[3 * D_ * D_];        // W^T (K-major)
__device__ __half g_woutT[D_ * D_];

// ---------------------------------------------------------------------------
// PTX helpers
// ---------------------------------------------------------------------------
__device__ __forceinline__ uint32_t smem_u32(const void* p) {
    return (uint32_t)__cvta_generic_to_shared(p);
}
__device__ __forceinline__ void cp_async16(uint32_t dst, const void* src) {
    asm volatile("cp.async.cg.shared.global [%0], [%1], 16;" :: "r"(dst), "l"(src));
}
__device__ __forceinline__ void cp_commit() {
    asm volatile("cp.async.commit_group;" ::: "memory");
}
__device__ __forceinline__ void cp_wait1() {
    asm volatile("cp.async.wait_group 1;" ::: "memory");
}
__device__ __forceinline__ void cp_wait0() {
    asm volatile("cp.async.wait_group 0;" ::: "memory");
}
__device__ __forceinline__ void mma_f16(float* c, const uint32_t* a, const uint32_t* b) {
    asm("mma.sync.aligned.m16n8k16.row.col.f32.f16.f16.f32 "
        "{%0,%1,%2,%3}, {%4,%5,%6,%7}, {%8,%9}, {%0,%1,%2,%3};"
        : "+f"(c[0]), "+f"(c[1]), "+f"(c[2]), "+f"(c[3])
        : "r"(a[0]), "r"(a[1]), "r"(a[2]), "r"(a[3]),
          "r"(b[0]), "r"(b[1]));
}
__device__ __forceinline__ void ldsm_x4(uint32_t* r, uint32_t addr) {
    asm volatile("ldmatrix.sync.aligned.m8n8.x4.shared.b16 {%0,%1,%2,%3}, [%4];"
        : "=r"(r[0]), "=r"(r[1]), "=r"(r[2]), "=r"(r[3]) : "r"(addr));
}
__device__ __forceinline__ void ldsm_x4_t(uint32_t* r, uint32_t addr) {
    asm volatile("ldmatrix.sync.aligned.m8n8.x4.trans.shared.b16 {%0,%1,%2,%3}, [%4];"
        : "=r"(r[0]), "=r"(r[1]), "=r"(r[2]), "=r"(r[3]) : "r"(addr));
}

// ---------------------------------------------------------------------------
// Prep kernels: x -> half; W -> transposed half (K-major)
// ---------------------------------------------------------------------------
__global__ void cvt_x_kernel(const float* __restrict__ x)
{
    const long i = ((long)blockIdx.x * 256 + threadIdx.x) * 8;
    float4 v0 = *(const float4*)(x + i);
    float4 v1 = *(const float4*)(x + i + 4);
    __half2 h0 = __floats2half2_rn(v0.x, v0.y);
    __half2 h1 = __floats2half2_rn(v0.z, v0.w);
    __half2 h2 = __floats2half2_rn(v1.x, v1.y);
    __half2 h3 = __floats2half2_rn(v1.z, v1.w);
    uint4 u = make_uint4(*(uint32_t*)&h0, *(uint32_t*)&h1,
                         *(uint32_t*)&h2, *(uint32_t*)&h3);
    *(uint4*)&g_xc[i] = u;
}

__global__ void transpose_h(const float* __restrict__ W, int K, int N, int which)
{
    __shared__ __half t[32][33];
    __half* WT = which ? g_woutT : g_wqkvT;
    const int nb = blockIdx.x * 32, kb = blockIdx.y * 32;
    const int tx = threadIdx.x, ty = threadIdx.y;
#pragma unroll
    for (int j = 0; j < 32; j += 8)
        t[ty + j][tx] = __float2half_rn(W[(long)(kb + ty + j) * N + nb + tx]);
    __syncthreads();
#pragma unroll
    for (int j = 0; j < 32; j += 8)
        WT[(long)(nb + ty + j) * K + kb + tx] = t[tx][ty + j];
}

// ---------------------------------------------------------------------------
// fp16 GEMM (unchanged from R11): block 128x128x32, 8 warps (2m x 4n),
// m16n8k16, K-major half tiles pitch 80 B, 3-stage cp.async, 1 barrier/iter.
// MODE 0: A = g_attn, fp32 C = acc + bias.
// MODE 1: A = g_xc, scatter half(acc+bias) into g_q(*1/8)/g_k/g_v (B,H,S,HD).
// ---------------------------------------------------------------------------
#define BM 128
#define BN 128
#define BK 32
#define PITCHB 80
#define TS_B (BM * PITCHB)
#define STAGE_B (2 * TS_B)
#define NSTAGE 3
#define GEMM_SMEM_BYTES (NSTAGE * STAGE_B)   // 61440 B

template <int MODE>
__global__ __launch_bounds__(256, 2) void gemm_h(
    const float* __restrict__ bias, float* __restrict__ C,
    int M, int N, int K)
{
    extern __shared__ char smc[];
    const uint32_t sb = smem_u32(smc);

    const __half* Au = (MODE == 0) ? g_attn : g_xc;
    const __half* WT = (MODE == 0) ? g_woutT : g_wqkvT;

    const int tid = threadIdx.x;
    const int wid = tid >> 5;
    const int lane = tid & 31;
    const int g = lane >> 2;
    const int t4 = lane & 3;
    const int m0w = (wid >> 2) * 64;
    const int n0w = (wid & 3) * 32;
    const int bm = blockIdx.y * BM;
    const int bn = blockIdx.x * BN;

    const uint32_t a_off = (m0w + (lane & 15)) * PITCHB + (lane >> 4) * 16;
    const uint32_t bp_off =
        (n0w + (lane & 7) + ((lane >> 4) & 1) * 8) * PITCHB
        + ((lane >> 3) & 1) * 16;

    auto load_tile = [&](int it) {
        const int kb = it * BK;
        const uint32_t dstA = sb + (it % NSTAGE) * STAGE_B;
        const uint32_t dstB = dstA + TS_B;
#pragma unroll
        for (int c = 0; c < 2; ++c) {
            const int id = tid + c * 256;
            const int row = id >> 2;
            const int kc = id & 3;
            cp_async16(dstA + row * PITCHB + kc * 16,
                       Au + (long)(bm + row) * K + kb + kc * 8);
            cp_async16(dstB + row * PITCHB + kc * 16,
                       WT + (long)(bn + row) * K + kb + kc * 8);
        }
        cp_commit();
    };

    float acc[4][4][4];
#pragma unroll
    for (int ma = 0; ma < 4; ++ma)
#pragma unroll
        for (int na = 0; na < 4; ++na)
#pragma unroll
            for (int i = 0; i < 4; ++i) acc[ma][na][i] = 0.f;

    const int NIT = K / BK;
    load_tile(0);
    load_tile(1);

    for (int it = 0; it < NIT; ++it) {
        cp_wait1();
        __syncthreads();
        if (it + 2 < NIT) load_tile(it + 2);

        const uint32_t abase = sb + (it % NSTAGE) * STAGE_B + a_off;
        const uint32_t bbase = sb + (it % NSTAGE) * STAGE_B + TS_B + bp_off;
#pragma unroll
        for (int ks = 0; ks < 2; ++ks) {
            const int kB = ks * 32;
            uint32_t af[4][4];
            uint32_t bq[2][4];
#pragma unroll
            for (int ma = 0; ma < 4; ++ma)
                ldsm_x4(af[ma], abase + ma * (16 * PITCHB) + kB);
#pragma unroll
            for (int p = 0; p < 2; ++p)
                ldsm_x4(bq[p], bbase + p * (16 * PITCHB) + kB);
#pragma unroll
            for (int ma = 0; ma < 4; ++ma)
#pragma unroll
                for (int p = 0; p < 2; ++p) {
                    mma_f16(acc[ma][2 * p],     af[ma], &bq[p][0]);
                    mma_f16(acc[ma][2 * p + 1], af[ma], &bq[p][2]);
                }
        }
    }

    // --- epilogue ------------------------------------------------------------
#pragma unroll
    for (int na = 0; na < 4; ++na) {
        const int col = bn + n0w + na * 8 + 2 * t4;
        const float2 bx = *(const float2*)&bias[col];

        if (MODE == 0) {
#pragma unroll
            for (int ma = 0; ma < 4; ++ma) {
                const long r0 = bm + m0w + ma * 16 + g;
                *(float2*)&C[r0 * N + col] =
                    make_float2(acc[ma][na][0] + bx.x, acc[ma][na][1] + bx.y);
                *(float2*)&C[(r0 + 8) * N + col] =
                    make_float2(acc[ma][na][2] + bx.x, acc[ma][na][3] + bx.y);
            }
        } else {
            const int h = col / 192;
            const int rem = col - h * 192;
            const int which = rem >> 6;
            const int d = rem & 63;
            __half* dst = (which == 0) ? g_q : (which == 1) ? g_k : g_v;
            const float sc = (which == 0) ? 0.125f : 1.0f;
#pragma unroll
            for (int ma = 0; ma < 4; ++ma) {
                const int m = bm + m0w + ma * 16 + g;
                const int b = m >> 11;
                const int s = m & (S_ - 1);
                const long base = (((long)(b * H_ + h)) * S_ + s) * HD_ + d;
                *(__half2*)&dst[base] =
                    __floats2half2_rn((acc[ma][na][0] + bx.x) * sc,
                                      (acc[ma][na][1] + bx.y) * sc);
                *(__half2*)&dst[base + 8 * HD_] =
                    __floats2half2_rn((acc[ma][na][2] + bx.x) * sc,
                                      (acc[ma][na][3] + bx.y) * sc);
            }
        }
    }
}

// ---------------------------------------------------------------------------
// fp16 flash attention, v2:
//  - V stored NATURAL [kk][d] via cp.async; Phase-C B-frags via ldmatrix.trans
//    (scalar V-transpose eliminated).
//  - K/V tiles DOUBLE-BUFFERED: one commit-group per tile, prefetch of tile
//    kt+1 issued right after the single per-tile barrier and hidden behind
//    Phases A/B/C. One __syncthreads per tile.
// Only ceil(vlen/64) key tiles (exp underflow vs -1e6 mask is exactly 0).
// ---------------------------------------------------------------------------
#define QT 128
#define APH 72
#define APB 144                          // bytes per smem row
#define QS_B_OFF 0
#define SS_B_OFF (QT * APB)              // 18432
#define KV_OFF   (SS_B_OFF + QT * APB)   // 36864
#define KV_STAGE (2 * 64 * APB)          // K then V, 18432 B per stage
#define ATTN_SMEM_BYTES (KV_OFF + 2 * KV_STAGE)   // 73728 B

__global__ __launch_bounds__(256, 2) void attn_h(const int* __restrict__ val_lens)
{
    extern __shared__ char smc[];
    __half* Qs = (__half*)(smc + QS_B_OFF);
    __half* Ss = (__half*)(smc + SS_B_OFF);

    const int b  = blockIdx.x;           // batch fastest -> balanced waves
    const int h  = blockIdx.y;
    const int q0 = blockIdx.z * QT;
    const int vlen = val_lens[b];
    const int tid = threadIdx.x;
    const int wid = tid >> 5;
    const int lane = tid & 31;
    const int g = lane >> 2;
    const int t4 = lane & 3;
    const int m0 = wid * 16;

    const long headoff = ((long)(b * H_ + h)) * S_ * HD_;
    const __half* qbase = g_q + headoff;
    const __half* kbase = g_k + headoff;
    const __half* vbase = g_v + headoff;

    const uint32_t sb = smem_u32(smc);
    const uint32_t QS_B = sb + QS_B_OFF;
    const uint32_t SS_B = sb + SS_B_OFF;
    const uint32_t KV_B = sb + KV_OFF;

    // A-frag (Q and P): rows m0+(lane&15), 16B k-half select
    const uint32_t qa_off = (m0 + (lane & 15)) * APB + (lane >> 4) * 16;
    // K B-frag (non-trans, K natural = [n=kk][k=d]):
    const uint32_t nbp_off =
        ((lane & 7) + ((lane >> 4) & 1) * 8) * APB + ((lane >> 3) & 1) * 16;
    // V B-frag (TRANS, V natural = [k=kk][n=d]): k-row select + n-col select
    const uint32_t vt_off =
        ((lane & 7) + ((lane >> 3) & 1) * 8) * APB + ((lane >> 4) & 1) * 16;

    // K/V tile loader: 64 rows x 128 B each via cp.async, 4 chunks/thread,
    // single commit group per tile.
    auto load_kv = [&](int kt, int buf) {
        const uint32_t dstK = KV_B + buf * KV_STAGE;
        const uint32_t dstV = dstK + 64 * APB;
#pragma unroll
        for (int c = 0; c < 2; ++c) {
            const int id = tid + c * 256;
            const int r = id >> 3;
            const int dc = id & 7;
            cp_async16(dstK + r * APB + dc * 16,
                       kbase + (long)(kt * 64 + r) * HD_ + dc * 8);
            cp_async16(dstV + r * APB + dc * 16,
                       vbase + (long)(kt * 64 + r) * HD_ + dc * 8);
        }
        cp_commit();
    };

    // Load Q tile (half, pre-scaled)
    {
        const int r = tid >> 1;
        const int c0 = (tid & 1) * 32;
        const __half* src = qbase + (long)(q0 + r) * HD_ + c0;
        __half* dst = &Qs[r * APH + c0];
#pragma unroll
        for (int j = 0; j < 32; j += 8)
            *(uint4*)(dst + j) = *(const uint4*)(src + j);
    }

    float m_lo = -3.0e38f, m_hi = -3.0e38f;
    float l_lo = 0.f, l_hi = 0.f;
    float acc_o[8][4];
#pragma unroll
    for (int na = 0; na < 8; ++na)
#pragma unroll
        for (int i = 0; i < 4; ++i) acc_o[na][i] = 0.f;

    const int ntiles = (vlen + 63) >> 6;
    load_kv(0, 0);

    for (int kt = 0; kt < ntiles; ++kt) {
        const int buf = kt & 1;
        cp_wait0();          // only group kt in flight here
        __syncthreads();     // tile ready + prev-iter reads of buf^1 done
        if (kt + 1 < ntiles) load_kv(kt + 1, buf ^ 1);   // hidden behind A/B/C

        const uint32_t KS_B = KV_B + buf * KV_STAGE;
        const uint32_t VS_B = KS_B + 64 * APB;

        // --- Phase A: S = Q K^T ---
        float accs[8][4];
#pragma unroll
        for (int na = 0; na < 8; ++na)
#pragma unroll
            for (int i = 0; i < 4; ++i) accs[na][i] = 0.f;
#pragma unroll
        for (int ks = 0; ks < 4; ++ks) {
            const int kB = ks * 32;
            uint32_t af[4];
            ldsm_x4(af, QS_B + qa_off + kB);
#pragma unroll
            for (int p = 0; p < 4; ++p) {
                uint32_t bq[4];
                ldsm_x4(bq, KS_B + nbp_off + p * (16 * APB) + kB);
                mma_f16(accs[2 * p],     af, &bq[0]);
                mma_f16(accs[2 * p + 1], af, &bq[2]);
            }
        }

        {   // in-register masked online softmax (quad shfl reductions)
            const int cbase = kt * 64 + 2 * t4;
            float mx_lo = -3.0e38f, mx_hi = -3.0e38f;
#pragma unroll
            for (int na = 0; na < 8; ++na) {
                const int c0 = cbase + na * 8;
                if (c0 < vlen)     { mx_lo = fmaxf(mx_lo, accs[na][0]);
                                     mx_hi = fmaxf(mx_hi, accs[na][2]); }
                if (c0 + 1 < vlen) { mx_lo = fmaxf(mx_lo, accs[na][1]);
                                     mx_hi = fmaxf(mx_hi, accs[na][3]); }
            }
            mx_lo = fmaxf(mx_lo, __shfl_xor_sync(0xffffffffu, mx_lo, 1));
            mx_lo = fmaxf(mx_lo, __shfl_xor_sync(0xffffffffu, mx_lo, 2));
            mx_hi = fmaxf(mx_hi, __shfl_xor_sync(0xffffffffu, mx_hi, 1));
            mx_hi = fmaxf(mx_hi, __shfl_xor_sync(0xffffffffu, mx_hi, 2));

            const float mn_lo = fmaxf(m_lo, mx_lo);
            const float mn_hi = fmaxf(m_hi, mx_hi);
            const float al_lo = __expf(m_lo - mn_lo);
            const float al_hi = __expf(m_hi - mn_hi);

            float s_lo = 0.f, s_hi = 0.f;
#pragma unroll
            for (int na = 0; na < 8; ++na) {
                const int c0 = cbase + na * 8;
                const float p0 = (c0 < vlen)     ? __expf(accs[na][0] - mn_lo) : 0.f;
                const float p1 = (c0 + 1 < vlen) ? __expf(accs[na][1] - mn_lo) : 0.f;
                const float p2 = (c0 < vlen)     ? __expf(accs[na][2] - mn_hi) : 0.f;
                const float p3 = (c0 + 1 < vlen) ? __expf(accs[na][3] - mn_hi) : 0.f;
                s_lo += p0 + p1;
                s_hi += p2 + p3;
                *(__half2*)&Ss[(m0 + g) * APH + na * 8 + 2 * t4] =
                    __floats2half2_rn(p0, p1);
                *(__half2*)&Ss[(m0 + g + 8) * APH + na * 8 + 2 * t4] =
                    __floats2half2_rn(p2, p3);
            }
            s_lo += __shfl_xor_sync(0xffffffffu, s_lo, 1);
            s_lo += __shfl_xor_sync(0xffffffffu, s_lo, 2);
            s_hi += __shfl_xor_sync(0xffffffffu, s_hi, 1);
            s_hi += __shfl_xor_sync(0xffffffffu, s_hi, 2);

            l_lo = l_lo * al_lo + s_lo;
            l_hi = l_hi * al_hi + s_hi;
            m_lo = mn_lo;
            m_hi = mn_hi;

#pragma unroll
            for (int na = 0; na < 8; ++na) {
                acc_o[na][0] *= al_lo; acc_o[na][1] *= al_lo;
                acc_o[na][2] *= al_hi; acc_o[na][3] *= al_hi;
            }
        }
        __syncwarp();   // Ss rows are warp-private; make STS visible to LDSM

        // --- Phase C: O += P V  (V natural, trans ldmatrix) ---
#pragma unroll
        for (int ks = 0; ks < 4; ++ks) {
            uint32_t af[4];
            ldsm_x4(af, SS_B + qa_off + ks * 32);
#pragma unroll
            for (int p = 0; p < 4; ++p) {
                uint32_t bq[4];
                ldsm_x4_t(bq, VS_B + vt_off + ks * (16 * APB) + p * 32);
                mma_f16(acc_o[2 * p],     af, &bq[0]);
                mma_f16(acc_o[2 * p + 1], af, &bq[2]);
            }
        }
        // no trailing barrier: next iter's top barrier orders buffer reuse
    }

    // --- epilogue: normalize, write g_attn (half, B,S,D) ---
    {
        const float li_lo = 1.0f / l_lo;
        const float li_hi = 1.0f / l_hi;
        const long r0 = (long)b * S_ + q0 + m0 + g;
#pragma unroll
        for (int na = 0; na < 8; ++na) {
            const int col = h * HD_ + na * 8 + 2 * t4;
            *(__half2*)&g_attn[r0 * D_ + col] =
                __floats2half2_rn(acc_o[na][0] * li_lo, acc_o[na][1] * li_lo);
            *(__half2*)&g_attn[(r0 + 8) * D_ + col] =
                __floats2half2_rn(acc_o[na][2] * li_hi, acc_o[na][3] * li_hi);
        }
    }
}

// ---------------------------------------------------------------------------
// Host launcher (graph-capturable: kernel launches only, no allocs/syncs)
// ---------------------------------------------------------------------------
extern "C" void kernel_launch(void* const* d_in, const int* in_sizes, int n_in,
                              void* d_out, int out_size)
{
    const float* x        = (const float*)d_in[0];
    const float* Wqkv     = (const float*)d_in[1];
    const float* bqkv     = (const float*)d_in[2];
    const float* Wout     = (const float*)d_in[3];
    const float* bout     = (const float*)d_in[4];
    const int*   val_lens = (const int*)d_in[5];
    float* out = (float*)d_out;

    cudaFuncSetAttribute(gemm_h<1>,
                         cudaFuncAttributeMaxDynamicSharedMemorySize, GEMM_SMEM_BYTES);
    cudaFuncSetAttribute(gemm_h<0>,
                         cudaFuncAttributeMaxDynamicSharedMemorySize, GEMM_SMEM_BYTES);
    cudaFuncSetAttribute(attn_h,
                         cudaFuncAttributeMaxDynamicSharedMemorySize, ATTN_SMEM_BYTES);

    // 0) Prep: fp16 conversions/transposes
    cvt_x_kernel<<<(B_ * S_ * D_) / (256 * 8), 256>>>(x);
    {
        dim3 blk(32, 8);
        transpose_h<<<dim3((3 * D_) / 32, D_ / 32), blk>>>(Wqkv, D_, 3 * D_, 0);
        transpose_h<<<dim3(D_ / 32, D_ / 32), blk>>>(Wout, D_, D_, 1);
    }
    // 1) QKV projection -> half Q/K/V in (B,H,S,HD)
    {
        dim3 grid((3 * D_) / BN, (B_ * S_) / BM);   // 24 x 64
        gemm_h<1><<<grid, 256, GEMM_SMEM_BYTES>>>(bqkv, nullptr, B_ * S_, 3 * D_, D_);
    }
    // 2) Flash attention -> g_attn (half)
    {
        dim3 grid(B_, H_, S_ / QT);                 // batch-fastest
        attn_h<<<grid, 256, ATTN_SMEM_BYTES>>>(val_lens);
    }
    // 3) Output projection -> d_out (fp32 + bias)
    {
        dim3 grid(D_ / BN, (B_ * S_) / BM);         // 8 x 64
        gemm_h<0><<<grid, 256, GEMM_SMEM_BYTES>>>(bout, out, B_ * S_, D_, D_);
    }
}